// round 11
// baseline (speedup 1.0000x reference)
#include <cuda_runtime.h>
#include <cuda_bf16.h>
#include <math.h>
#include <cstdint>

#define D 128
#define MAX_NODES 50000
#define MAX_EDGES 640000
#define MAX_GRAPHS 500
#define BN_EPS 1e-5f

// ---------------- scratch ----------------------------------------------------
__device__ float g_h   [MAX_NODES * D];
__device__ float g_x1  [MAX_NODES * D];
__device__ float g_x2  [MAX_NODES * D];
__device__ float g_pool[MAX_GRAPHS * D];
__device__ float g_w1t [3 * D * D];
__device__ float g_w2t [3 * D * D];
__device__ int   g_cnt [MAX_NODES];
__device__ int   g_rowptr[MAX_NODES + 1];
__device__ int   g_tick[MAX_EDGES];
__device__ int   g_csrsrc[MAX_EDGES];

// ---------------- stream/event pool (created at load, before any checkpoint) --
struct PipeRes {
    cudaStream_t s2;
    cudaEvent_t ev[8];
    PipeRes() {
        cudaStreamCreateWithFlags(&s2, cudaStreamNonBlocking);
        for (int i = 0; i < 8; i++)
            cudaEventCreateWithFlags(&ev[i], cudaEventDisableTiming);
    }
};
static PipeRes g_pipe;

// ---------------- helpers ----------------------------------------------------
__device__ __forceinline__ float tf32r(float v) {
    float o;
    asm("cvt.rna.tf32.f32 %0, %1;" : "=f"(o) : "f"(v));
    return o;
}
__device__ __forceinline__ void red_add_v2(float* p, float a, float b) {
    asm volatile("red.global.add.v2.f32 [%0], {%1,%2};"
                 :: "l"(p), "f"(a), "f"(b) : "memory");
}
__device__ __forceinline__ void mma_tf32(float* d, const uint32_t* a, const uint32_t* b) {
    asm volatile(
        "mma.sync.aligned.m16n8k8.row.col.f32.tf32.tf32.f32 "
        "{%0,%1,%2,%3}, {%4,%5,%6,%7}, {%8,%9}, {%0,%1,%2,%3};"
        : "+f"(d[0]), "+f"(d[1]), "+f"(d[2]), "+f"(d[3])
        : "r"(a[0]), "r"(a[1]), "r"(a[2]), "r"(a[3]), "r"(b[0]), "r"(b[1]));
}

// ---------------- CSR build ---------------------------------------------------
__global__ void hist_kernel(const int* __restrict__ dst, int* __restrict__ cnt,
                            int* __restrict__ tick, int nEdges) {
    int e = blockIdx.x * blockDim.x + threadIdx.x;
    if (e < nEdges) tick[e] = atomicAdd(&cnt[dst[e]], 1);
}

__global__ void scan_kernel(const int* __restrict__ cnt, int* __restrict__ rowptr, int n) {
    __shared__ int part[1024];
    int tid = threadIdx.x;
    int chunk = (n + 1023) / 1024;
    int beg = tid * chunk;
    int end = beg + chunk < n ? beg + chunk : n;
    int s = 0;
    for (int i = beg; i < end; i++) s += cnt[i];
    part[tid] = s;
    __syncthreads();
    for (int off = 1; off < 1024; off <<= 1) {
        int v = (tid >= off) ? part[tid - off] : 0;
        __syncthreads();
        part[tid] += v;
        __syncthreads();
    }
    int base = (tid > 0) ? part[tid - 1] : 0;
    for (int i = beg; i < end; i++) {
        rowptr[i] = base;
        base += cnt[i];
    }
    if (tid == 1023) rowptr[n] = part[1023];
}

__global__ void fill_kernel(const int* __restrict__ src, const int* __restrict__ dst,
                            const int* __restrict__ rowptr, const int* __restrict__ tick,
                            int* __restrict__ csrsrc, int nEdges) {
    int e = blockIdx.x * blockDim.x + threadIdx.x;
    if (e < nEdges) csrsrc[rowptr[dst[e]] + tick[e]] = src[e];
}

// ---------------- weight prep: transpose + tf32 round ------------------------
__global__ void wprep_kernel(const float* __restrict__ W1, const float* __restrict__ W2,
                             float* __restrict__ w1t, float* __restrict__ w2t) {
    __shared__ float tile[32][33];
    int z = blockIdx.z;
    const float* src = (z < 3) ? (W1 + z * D * D) : (W2 + (z - 3) * D * D);
    float*       dstp = (z < 3) ? (w1t + z * D * D) : (w2t + (z - 3) * D * D);
    int x0 = blockIdx.x * 32, y0 = blockIdx.y * 32;
    int tx = threadIdx.x, ty = threadIdx.y;
    #pragma unroll
    for (int j = 0; j < 4; j++)
        tile[ty + j * 8][tx] = src[(y0 + ty + j * 8) * D + x0 + tx];
    __syncthreads();
    #pragma unroll
    for (int j = 0; j < 4; j++)
        dstp[(x0 + ty + j * 8) * D + y0 + tx] = tf32r(tile[tx][ty + j * 8]);
}

// ---------------- gather over node range [base, endNode) ----------------------
__global__ __launch_bounds__(256)
void gather_kernel(const float* __restrict__ x,
                   const int* __restrict__ rowptr,
                   const int* __restrict__ csrsrc,
                   float* __restrict__ h, int base, int endNode) {
    int gid  = blockIdx.x * blockDim.x + threadIdx.x;
    int node = base + (gid >> 5);
    int lane = gid & 31;
    if (node >= endNode) return;
    const float4* x4 = (const float4*)x;
    float4 a0 = x4[(size_t)node * 32 + lane];
    float4 a1 = make_float4(0.f, 0.f, 0.f, 0.f);
    float4 a2 = make_float4(0.f, 0.f, 0.f, 0.f);
    float4 a3 = make_float4(0.f, 0.f, 0.f, 0.f);
    int beg = rowptr[node];
    int end = rowptr[node + 1];
    int e = beg;
    for (; e + 3 < end; e += 4) {
        int s0 = csrsrc[e], s1 = csrsrc[e + 1], s2 = csrsrc[e + 2], s3 = csrsrc[e + 3];
        float4 v0 = x4[(size_t)s0 * 32 + lane];
        float4 v1 = x4[(size_t)s1 * 32 + lane];
        float4 v2 = x4[(size_t)s2 * 32 + lane];
        float4 v3 = x4[(size_t)s3 * 32 + lane];
        a0.x += v0.x; a0.y += v0.y; a0.z += v0.z; a0.w += v0.w;
        a1.x += v1.x; a1.y += v1.y; a1.z += v1.z; a1.w += v1.w;
        a2.x += v2.x; a2.y += v2.y; a2.z += v2.z; a2.w += v2.w;
        a3.x += v3.x; a3.y += v3.y; a3.z += v3.z; a3.w += v3.w;
    }
    for (; e < end; e++) {
        int s0 = csrsrc[e];
        float4 v0 = x4[(size_t)s0 * 32 + lane];
        a0.x += v0.x; a0.y += v0.y; a0.z += v0.z; a0.w += v0.w;
    }
    float4 hv;
    hv.x = tf32r((a0.x + a1.x) + (a2.x + a3.x));
    hv.y = tf32r((a0.y + a1.y) + (a2.y + a3.y));
    hv.z = tf32r((a0.z + a1.z) + (a2.z + a3.z));
    hv.w = tf32r((a0.w + a1.w) + (a2.w + a3.w));
    ((float4*)h)[(size_t)node * 32 + lane] = hv;
}

// ---------------- fused MLP layer, TILE_M=64, 2 CTAs/SM -----------------------
#define TILE_M 64
#define LDS_STRIDE 132
#define A_FLOATS (TILE_M * LDS_STRIDE)
#define B_FLOATS (128 * LDS_STRIDE)
#define P_FLOATS (5 * 128)
#define SMEM_TOTAL_MLP ((A_FLOATS + B_FLOATS + P_FLOATS) * 4)

__global__ __launch_bounds__(256, 2)
void mlp_mma_kernel(const float* __restrict__ hin,
                    const float* __restrict__ w1t, const float* __restrict__ b1,
                    const float* __restrict__ w2t, const float* __restrict__ b2,
                    const float* __restrict__ bns, const float* __restrict__ bnb,
                    const float* __restrict__ bnm, const float* __restrict__ bnv,
                    float* __restrict__ xout,
                    const int* __restrict__ batch, float* __restrict__ pool,
                    int poolMode, int rowBase, int nNodes) {
    extern __shared__ float smem[];
    float* As  = smem;
    float* Bs  = smem + A_FLOATS;
    float* sb1 = smem + A_FLOATS + B_FLOATS;
    float* sb2 = sb1 + 128;
    float* skk = sb2 + 128;
    float* smm = skk + 128;
    float* scc = smm + 128;

    int tid  = threadIdx.x;
    int wid  = tid >> 5;
    int lane = tid & 31;
    int mg   = wid >> 2;
    int ng   = wid & 3;
    int gp   = lane >> 2;
    int tq   = lane & 3;
    int row0 = rowBase + blockIdx.x * TILE_M;

    if (tid < 128) {
        sb1[tid] = b1[tid];
        sb2[tid] = b2[tid];
        skk[tid] = bns[tid] * rsqrtf(bnv[tid] + BN_EPS);
        smm[tid] = bnm[tid];
        scc[tid] = bnb[tid];
    }

    const float4* h4  = (const float4*)hin;
    const float4* w14 = (const float4*)w1t;
    #pragma unroll
    for (int it = 0; it < 8; it++) {
        int i = tid + it * 256;
        int row = i >> 5, c4 = i & 31;
        int gr = row0 + row;
        float4 hv = make_float4(0.f, 0.f, 0.f, 0.f);
        if (gr < nNodes) hv = h4[(size_t)gr * 32 + c4];
        *(float4*)(As + row * LDS_STRIDE + c4 * 4) = hv;
    }
    #pragma unroll
    for (int it = 0; it < 16; it++) {
        int i = tid + it * 256;
        int row = i >> 5, c4 = i & 31;
        *(float4*)(Bs + row * LDS_STRIDE + c4 * 4) = w14[i];
    }
    __syncthreads();

    float acc[2][4][4];
    #pragma unroll
    for (int mi = 0; mi < 2; mi++)
        #pragma unroll
        for (int ni = 0; ni < 4; ni++)
            #pragma unroll
            for (int c = 0; c < 4; c++) acc[mi][ni][c] = 0.f;

    // ---- GEMM 1: T = H @ W1 -------------------------------------------------
    #pragma unroll
    for (int s = 0; s < 16; s++) {
        int k0 = s * 8;
        uint32_t afr[2][4], bfr[4][2];
        #pragma unroll
        for (int mi = 0; mi < 2; mi++) {
            const float* ap = As + (mg * 32 + mi * 16 + gp) * LDS_STRIDE + k0 + tq;
            afr[mi][0] = __float_as_uint(ap[0]);
            afr[mi][1] = __float_as_uint(ap[8 * LDS_STRIDE]);
            afr[mi][2] = __float_as_uint(ap[4]);
            afr[mi][3] = __float_as_uint(ap[8 * LDS_STRIDE + 4]);
        }
        #pragma unroll
        for (int ni = 0; ni < 4; ni++) {
            const float* bp = Bs + (ng * 32 + ni * 8 + gp) * LDS_STRIDE + k0 + tq;
            bfr[ni][0] = __float_as_uint(bp[0]);
            bfr[ni][1] = __float_as_uint(bp[4]);
        }
        #pragma unroll
        for (int mi = 0; mi < 2; mi++)
            #pragma unroll
            for (int ni = 0; ni < 4; ni++)
                mma_tf32(acc[mi][ni], afr[mi], bfr[ni]);
    }
    __syncthreads();

    // ---- epilogue 1 -> As ---------------------------------------------------
    #pragma unroll
    for (int mi = 0; mi < 2; mi++) {
        #pragma unroll
        for (int ni = 0; ni < 4; ni++) {
            int col = ng * 32 + ni * 8 + tq * 2;
            int r0  = mg * 32 + mi * 16 + gp;
            float t0 = acc[mi][ni][0] + sb1[col];
            float t1 = acc[mi][ni][1] + sb1[col + 1];
            float t2 = acc[mi][ni][2] + sb1[col];
            float t3 = acc[mi][ni][3] + sb1[col + 1];
            float2 v01 = make_float2(tf32r(t0 > 0.f ? t0 : 0.f), tf32r(t1 > 0.f ? t1 : 0.f));
            float2 v23 = make_float2(tf32r(t2 > 0.f ? t2 : 0.f), tf32r(t3 > 0.f ? t3 : 0.f));
            *(float2*)(As + r0 * LDS_STRIDE + col)       = v01;
            *(float2*)(As + (r0 + 8) * LDS_STRIDE + col) = v23;
            acc[mi][ni][0] = 0.f; acc[mi][ni][1] = 0.f;
            acc[mi][ni][2] = 0.f; acc[mi][ni][3] = 0.f;
        }
    }
    {
        const float4* w24 = (const float4*)w2t;
        #pragma unroll
        for (int it = 0; it < 16; it++) {
            int i = tid + it * 256;
            int row = i >> 5, c4 = i & 31;
            *(float4*)(Bs + row * LDS_STRIDE + c4 * 4) = w24[i];
        }
    }
    __syncthreads();

    // ---- GEMM 2: Y = T @ W2 -------------------------------------------------
    #pragma unroll
    for (int s = 0; s < 16; s++) {
        int k0 = s * 8;
        uint32_t afr[2][4], bfr[4][2];
        #pragma unroll
        for (int mi = 0; mi < 2; mi++) {
            const float* ap = As + (mg * 32 + mi * 16 + gp) * LDS_STRIDE + k0 + tq;
            afr[mi][0] = __float_as_uint(ap[0]);
            afr[mi][1] = __float_as_uint(ap[8 * LDS_STRIDE]);
            afr[mi][2] = __float_as_uint(ap[4]);
            afr[mi][3] = __float_as_uint(ap[8 * LDS_STRIDE + 4]);
        }
        #pragma unroll
        for (int ni = 0; ni < 4; ni++) {
            const float* bp = Bs + (ng * 32 + ni * 8 + gp) * LDS_STRIDE + k0 + tq;
            bfr[ni][0] = __float_as_uint(bp[0]);
            bfr[ni][1] = __float_as_uint(bp[4]);
        }
        #pragma unroll
        for (int mi = 0; mi < 2; mi++)
            #pragma unroll
            for (int ni = 0; ni < 4; ni++)
                mma_tf32(acc[mi][ni], afr[mi], bfr[ni]);
    }

    // ---- epilogue 2: bias + BN + relu -> gmem (or pool via RED) -------------
    #pragma unroll
    for (int mi = 0; mi < 2; mi++) {
        #pragma unroll
        for (int ni = 0; ni < 4; ni++) {
            int col = ng * 32 + ni * 8 + tq * 2;
            int r0  = mg * 32 + mi * 16 + gp;
            int gr0 = row0 + r0;
            int gr1 = gr0 + 8;
            float kk0 = skk[col], kk1 = skk[col + 1];
            float t;
            float2 v;
            if (gr0 < nNodes) {
                t = (acc[mi][ni][0] + sb2[col]     - smm[col])     * kk0 + scc[col];
                v.x = t > 0.f ? t : 0.f;
                t = (acc[mi][ni][1] + sb2[col + 1] - smm[col + 1]) * kk1 + scc[col + 1];
                v.y = t > 0.f ? t : 0.f;
                if (poolMode) red_add_v2(pool + (size_t)batch[gr0] * D + col, v.x, v.y);
                else          *(float2*)(xout + (size_t)gr0 * D + col) = v;
            }
            if (gr1 < nNodes) {
                t = (acc[mi][ni][2] + sb2[col]     - smm[col])     * kk0 + scc[col];
                v.x = t > 0.f ? t : 0.f;
                t = (acc[mi][ni][3] + sb2[col + 1] - smm[col + 1]) * kk1 + scc[col + 1];
                v.y = t > 0.f ? t : 0.f;
                if (poolMode) red_add_v2(pool + (size_t)batch[gr1] * D + col, v.x, v.y);
                else          *(float2*)(xout + (size_t)gr1 * D + col) = v;
            }
        }
    }
}

// ---------------- head --------------------------------------------------------
#define HID 64
#define NCLS 12
__global__ void head_kernel(const float* __restrict__ pool,
                            const float* __restrict__ Wh1, const float* __restrict__ bh1,
                            const float* __restrict__ Wh2, const float* __restrict__ bh2,
                            float* __restrict__ out, int nGraphs) {
    __shared__ float sg[D];
    __shared__ float sh1[HID];
    int g = blockIdx.x;
    if (g >= nGraphs) return;
    int tid = threadIdx.x;
    sg[tid]       = pool[g * D + tid];
    sg[tid + HID] = pool[g * D + tid + HID];
    __syncthreads();
    float a = bh1[tid];
    #pragma unroll 4
    for (int k = 0; k < D; k++) a += sg[k] * Wh1[k * HID + tid];
    sh1[tid] = a > 0.f ? a : 0.f;
    __syncthreads();
    if (tid < NCLS) {
        float o = bh2[tid];
        #pragma unroll
        for (int k = 0; k < HID; k++) o += sh1[k] * Wh2[k * NCLS + tid];
        out[g * NCLS + tid] = 1.f / (1.f + expf(-o));
    }
}

// ---------------- launcher ---------------------------------------------------
extern "C" void kernel_launch(void* const* d_in, const int* in_sizes, int n_in,
                              void* d_out, int out_size) {
    const float* x     = (const float*)d_in[0];
    const int*   ei    = (const int*)d_in[1];
    const int*   batch = (const int*)d_in[2];
    const float* W1    = (const float*)d_in[3];
    const float* b1    = (const float*)d_in[4];
    const float* W2    = (const float*)d_in[5];
    const float* b2    = (const float*)d_in[6];
    const float* bns   = (const float*)d_in[7];
    const float* bnb   = (const float*)d_in[8];
    const float* bnm   = (const float*)d_in[9];
    const float* bnv   = (const float*)d_in[10];
    const float* Wh1   = (const float*)d_in[11];
    const float* bh1   = (const float*)d_in[12];
    const float* Wh2   = (const float*)d_in[13];
    const float* bh2   = (const float*)d_in[14];
    float* out = (float*)d_out;

    int nNodes  = in_sizes[0] / D;
    int nEdges  = in_sizes[1] / 2;
    int nGraphs = out_size / NCLS;

    const int* src = ei;
    const int* dst = ei + nEdges;

    float *h, *x1, *x2, *pool, *w1t, *w2t;
    int *cnt, *rowptr, *tick, *csrsrc;
    cudaGetSymbolAddress((void**)&h,      g_h);
    cudaGetSymbolAddress((void**)&x1,     g_x1);
    cudaGetSymbolAddress((void**)&x2,     g_x2);
    cudaGetSymbolAddress((void**)&pool,   g_pool);
    cudaGetSymbolAddress((void**)&w1t,    g_w1t);
    cudaGetSymbolAddress((void**)&w2t,    g_w2t);
    cudaGetSymbolAddress((void**)&cnt,    g_cnt);
    cudaGetSymbolAddress((void**)&rowptr, g_rowptr);
    cudaGetSymbolAddress((void**)&tick,   g_tick);
    cudaGetSymbolAddress((void**)&csrsrc, g_csrsrc);

    cudaFuncSetAttribute(mlp_mma_kernel, cudaFuncAttributeMaxDynamicSharedMemorySize,
                         SMEM_TOTAL_MLP);

    cudaStream_t s0 = 0;
    cudaStream_t s2 = g_pipe.s2;

    // ---- prologue: fork wprep + pool memset (s2) vs CSR chain (s0) ----------
    cudaEventRecord(g_pipe.ev[6], s0);
    cudaStreamWaitEvent(s2, g_pipe.ev[6], 0);
    wprep_kernel<<<dim3(4, 4, 6), dim3(32, 8), 0, s2>>>(W1, W2, w1t, w2t);
    cudaMemsetAsync(pool, 0, (size_t)nGraphs * D * sizeof(float), s2);
    cudaEventRecord(g_pipe.ev[7], s2);

    cudaMemsetAsync(cnt, 0, (size_t)nNodes * sizeof(int), s0);
    int eb = (nEdges + 255) / 256;
    hist_kernel<<<eb, 256, 0, s0>>>(dst, cnt, tick, nEdges);
    scan_kernel<<<1, 1024, 0, s0>>>(cnt, rowptr, nNodes);
    fill_kernel<<<eb, 256, 0, s0>>>(src, dst, rowptr, tick, csrsrc, nEdges);
    cudaStreamWaitEvent(s0, g_pipe.ev[7], 0);

    // ---- layers: split-half pipeline ----------------------------------------
    int nBlk   = (nNodes + TILE_M - 1) / TILE_M;
    int blkLo  = nBlk / 2;
    int blkHi  = nBlk - blkLo;
    int nsplit = blkLo * TILE_M;

    const float* xs[3] = { x, x1, x2 };
    float*       xd[3] = { x1, x2, x1 };

    for (int l = 0; l < 3; l++) {
        // gather half0 on s0
        gather_kernel<<<(nsplit + 7) / 8, 256, 0, s0>>>(xs[l], rowptr, csrsrc, h, 0, nsplit);
        cudaEventRecord(g_pipe.ev[2 * l], s0);
        // gather half1 on s2 (overlaps mlp half0)
        cudaStreamWaitEvent(s2, g_pipe.ev[2 * l], 0);
        gather_kernel<<<((nNodes - nsplit) + 7) / 8, 256, 0, s2>>>(xs[l], rowptr, csrsrc, h,
                                                                   nsplit, nNodes);
        cudaEventRecord(g_pipe.ev[2 * l + 1], s2);
        // mlp half0 on s0
        mlp_mma_kernel<<<blkLo, 256, SMEM_TOTAL_MLP, s0>>>(
            h, w1t + l * D * D, b1 + l * D, w2t + l * D * D, b2 + l * D,
            bns + l * D, bnb + l * D, bnm + l * D, bnv + l * D,
            xd[l], batch, pool, (l == 2) ? 1 : 0, 0, nNodes);
        // join gather half1, then mlp half1 on s0
        cudaStreamWaitEvent(s0, g_pipe.ev[2 * l + 1], 0);
        mlp_mma_kernel<<<blkHi, 256, SMEM_TOTAL_MLP, s0>>>(
            h, w1t + l * D * D, b1 + l * D, w2t + l * D * D, b2 + l * D,
            bns + l * D, bnb + l * D, bnm + l * D, bnv + l * D,
            xd[l], batch, pool, (l == 2) ? 1 : 0, nsplit, nNodes);
    }

    head_kernel<<<nGraphs, HID, 0, s0>>>(pool, Wh1, bh1, Wh2, bh2, out, nGraphs);
}

// round 12
// speedup vs baseline: 1.0853x; 1.0853x over previous
#include <cuda_runtime.h>
#include <cuda_bf16.h>
#include <math.h>
#include <cstdint>

#define D 128
#define MAX_NODES 50000
#define MAX_EDGES 640000
#define MAX_GRAPHS 500
#define BN_EPS 1e-5f

// ---------------- scratch ----------------------------------------------------
__device__ float g_h   [MAX_NODES * D];
__device__ float g_x1  [MAX_NODES * D];
__device__ float g_x2  [MAX_NODES * D];
__device__ float g_pool[MAX_GRAPHS * D];
__device__ float g_w1t [3 * D * D];
__device__ float g_w2t [3 * D * D];
__device__ int   g_cnt [MAX_NODES];
__device__ int   g_rowptr[MAX_NODES + 1];
__device__ int   g_tick[MAX_EDGES];
__device__ int   g_csrsrc[MAX_EDGES];

// ---------------- helpers ----------------------------------------------------
__device__ __forceinline__ float tf32r(float v) {
    float o;
    asm("cvt.rna.tf32.f32 %0, %1;" : "=f"(o) : "f"(v));
    return o;
}
__device__ __forceinline__ void red_add_v2(float* p, float a, float b) {
    asm volatile("red.global.add.v2.f32 [%0], {%1,%2};"
                 :: "l"(p), "f"(a), "f"(b) : "memory");
}
__device__ __forceinline__ void mma_tf32(float* d, const uint32_t* a, const uint32_t* b) {
    asm volatile(
        "mma.sync.aligned.m16n8k8.row.col.f32.tf32.tf32.f32 "
        "{%0,%1,%2,%3}, {%4,%5,%6,%7}, {%8,%9}, {%0,%1,%2,%3};"
        : "+f"(d[0]), "+f"(d[1]), "+f"(d[2]), "+f"(d[3])
        : "r"(a[0]), "r"(a[1]), "r"(a[2]), "r"(a[3]), "r"(b[0]), "r"(b[1]));
}

// ---------------- CSR build ---------------------------------------------------
__global__ void hist_kernel(const int* __restrict__ dst, int* __restrict__ cnt,
                            int* __restrict__ tick, int nEdges) {
    int e = blockIdx.x * blockDim.x + threadIdx.x;
    if (e < nEdges) tick[e] = atomicAdd(&cnt[dst[e]], 1);
}

__global__ void scan_kernel(const int* __restrict__ cnt, int* __restrict__ rowptr, int n) {
    __shared__ int part[1024];
    int tid = threadIdx.x;
    int chunk = (n + 1023) / 1024;
    int beg = tid * chunk;
    int end = beg + chunk < n ? beg + chunk : n;
    int s = 0;
    for (int i = beg; i < end; i++) s += cnt[i];
    part[tid] = s;
    __syncthreads();
    for (int off = 1; off < 1024; off <<= 1) {
        int v = (tid >= off) ? part[tid - off] : 0;
        __syncthreads();
        part[tid] += v;
        __syncthreads();
    }
    int base = (tid > 0) ? part[tid - 1] : 0;
    for (int i = beg; i < end; i++) {
        rowptr[i] = base;
        base += cnt[i];
    }
    if (tid == 1023) rowptr[n] = part[1023];
}

__global__ void fill_kernel(const int* __restrict__ src, const int* __restrict__ dst,
                            const int* __restrict__ rowptr, const int* __restrict__ tick,
                            int* __restrict__ csrsrc, int nEdges) {
    int e = blockIdx.x * blockDim.x + threadIdx.x;
    if (e < nEdges) csrsrc[rowptr[dst[e]] + tick[e]] = src[e];
}

// ---------------- weight prep: transpose + tf32 round ------------------------
__global__ void wprep_kernel(const float* __restrict__ W1, const float* __restrict__ W2,
                             float* __restrict__ w1t, float* __restrict__ w2t) {
    __shared__ float tile[32][33];
    int z = blockIdx.z;
    const float* src = (z < 3) ? (W1 + z * D * D) : (W2 + (z - 3) * D * D);
    float*       dstp = (z < 3) ? (w1t + z * D * D) : (w2t + (z - 3) * D * D);
    int x0 = blockIdx.x * 32, y0 = blockIdx.y * 32;
    int tx = threadIdx.x, ty = threadIdx.y;
    #pragma unroll
    for (int j = 0; j < 4; j++)
        tile[ty + j * 8][tx] = src[(y0 + ty + j * 8) * D + x0 + tx];
    __syncthreads();
    #pragma unroll
    for (int j = 0; j < 4; j++)
        dstp[(x0 + ty + j * 8) * D + y0 + tx] = tf32r(tile[tx][ty + j * 8]);
}

// ---------------- gather: h[i] = tf32r( x[i] + sum_{e in CSR(i)} x[src] ) -----
__global__ __launch_bounds__(256)
void gather_kernel(const float* __restrict__ x,
                   const int* __restrict__ rowptr,
                   const int* __restrict__ csrsrc,
                   float* __restrict__ h, int nNodes) {
    int gid  = blockIdx.x * blockDim.x + threadIdx.x;
    int node = gid >> 5;
    int lane = gid & 31;
    if (node >= nNodes) return;
    const float4* x4 = (const float4*)x;
    float4 a0 = x4[(size_t)node * 32 + lane];
    float4 a1 = make_float4(0.f, 0.f, 0.f, 0.f);
    float4 a2 = make_float4(0.f, 0.f, 0.f, 0.f);
    float4 a3 = make_float4(0.f, 0.f, 0.f, 0.f);
    int beg = rowptr[node];
    int end = rowptr[node + 1];
    int e = beg;
    for (; e + 3 < end; e += 4) {
        int s0 = csrsrc[e], s1 = csrsrc[e + 1], s2 = csrsrc[e + 2], s3 = csrsrc[e + 3];
        float4 v0 = x4[(size_t)s0 * 32 + lane];
        float4 v1 = x4[(size_t)s1 * 32 + lane];
        float4 v2 = x4[(size_t)s2 * 32 + lane];
        float4 v3 = x4[(size_t)s3 * 32 + lane];
        a0.x += v0.x; a0.y += v0.y; a0.z += v0.z; a0.w += v0.w;
        a1.x += v1.x; a1.y += v1.y; a1.z += v1.z; a1.w += v1.w;
        a2.x += v2.x; a2.y += v2.y; a2.z += v2.z; a2.w += v2.w;
        a3.x += v3.x; a3.y += v3.y; a3.z += v3.z; a3.w += v3.w;
    }
    for (; e < end; e++) {
        int s0 = csrsrc[e];
        float4 v0 = x4[(size_t)s0 * 32 + lane];
        a0.x += v0.x; a0.y += v0.y; a0.z += v0.z; a0.w += v0.w;
    }
    float4 hv;
    hv.x = tf32r((a0.x + a1.x) + (a2.x + a3.x));
    hv.y = tf32r((a0.y + a1.y) + (a2.y + a3.y));
    hv.z = tf32r((a0.z + a1.z) + (a2.z + a3.z));
    hv.w = tf32r((a0.w + a1.w) + (a2.w + a3.w));
    ((float4*)h)[(size_t)node * 32 + lane] = hv;
}

// ---------------- persistent fused MLP layer ----------------------------------
// 512 threads, 1 CTA/SM, weights resident in smem, grid-stride over 128-row tiles
#define TILE_M 128
#define LDS_STRIDE 132
#define A_FLOATS (TILE_M * LDS_STRIDE)        // 16896
#define B_FLOATS (128 * LDS_STRIDE)           // 16896
#define P_FLOATS (5 * 128)
#define SMEM_TOTAL_MLP ((A_FLOATS + 2 * B_FLOATS + P_FLOATS) * 4)   // ~200.5 KB

__global__ __launch_bounds__(512, 1)
void mlp_mma_kernel(const float* __restrict__ hin,
                    const float* __restrict__ w1t, const float* __restrict__ b1,
                    const float* __restrict__ w2t, const float* __restrict__ b2,
                    const float* __restrict__ bns, const float* __restrict__ bnb,
                    const float* __restrict__ bnm, const float* __restrict__ bnv,
                    float* __restrict__ xout,
                    const int* __restrict__ batch, float* __restrict__ pool,
                    int poolMode, int nNodes) {
    extern __shared__ float smem[];
    float* As  = smem;                         // [128][132]
    float* B1s = smem + A_FLOATS;              // [128][132]
    float* B2s = B1s + B_FLOATS;               // [128][132]
    float* sb1 = B2s + B_FLOATS;
    float* sb2 = sb1 + 128;
    float* skk = sb2 + 128;
    float* smm = skk + 128;
    float* scc = smm + 128;

    int tid  = threadIdx.x;
    int wid  = tid >> 5;
    int lane = tid & 31;
    int mg   = wid >> 2;        // 0..3  (rows mg*32 .. +31)
    int ng   = wid & 3;         // 0..3  (cols ng*32 .. +31)
    int gp   = lane >> 2;       // 0..7
    int tq   = lane & 3;        // 0..3

    if (tid < 128) {
        sb1[tid] = b1[tid];
        sb2[tid] = b2[tid];
        skk[tid] = bns[tid] * rsqrtf(bnv[tid] + BN_EPS);
        smm[tid] = bnm[tid];
        scc[tid] = bnb[tid];
    }

    // ---- load both weight matrices ONCE -------------------------------------
    {
        const float4* w14 = (const float4*)w1t;
        const float4* w24 = (const float4*)w2t;
        #pragma unroll
        for (int it = 0; it < 8; it++) {
            int i = tid + it * 512;             // 128*32 = 4096 float4
            int row = i >> 5, c4 = i & 31;
            *(float4*)(B1s + row * LDS_STRIDE + c4 * 4) = w14[i];
            *(float4*)(B2s + row * LDS_STRIDE + c4 * 4) = w24[i];
        }
    }
    __syncthreads();

    const float4* h4 = (const float4*)hin;
    int nTiles = (nNodes + TILE_M - 1) / TILE_M;

    for (int tile = blockIdx.x; tile < nTiles; tile += gridDim.x) {
        int row0 = tile * TILE_M;

        // ---- load A tile -----------------------------------------------------
        #pragma unroll
        for (int it = 0; it < 8; it++) {
            int i = tid + it * 512;             // 128*32 float4
            int row = i >> 5, c4 = i & 31;
            int gr = row0 + row;
            float4 hv = make_float4(0.f, 0.f, 0.f, 0.f);
            if (gr < nNodes) hv = h4[(size_t)gr * 32 + c4];
            *(float4*)(As + row * LDS_STRIDE + c4 * 4) = hv;
        }
        __syncthreads();

        float acc[2][4][4];
        #pragma unroll
        for (int mi = 0; mi < 2; mi++)
            #pragma unroll
            for (int ni = 0; ni < 4; ni++)
                #pragma unroll
                for (int c = 0; c < 4; c++) acc[mi][ni][c] = 0.f;

        // ---- GEMM 1: T = H @ W1 ---------------------------------------------
        #pragma unroll
        for (int s = 0; s < 16; s++) {
            int k0 = s * 8;
            uint32_t afr[2][4], bfr[4][2];
            #pragma unroll
            for (int mi = 0; mi < 2; mi++) {
                const float* ap = As + (mg * 32 + mi * 16 + gp) * LDS_STRIDE + k0 + tq;
                afr[mi][0] = __float_as_uint(ap[0]);
                afr[mi][1] = __float_as_uint(ap[8 * LDS_STRIDE]);
                afr[mi][2] = __float_as_uint(ap[4]);
                afr[mi][3] = __float_as_uint(ap[8 * LDS_STRIDE + 4]);
            }
            #pragma unroll
            for (int ni = 0; ni < 4; ni++) {
                const float* bp = B1s + (ng * 32 + ni * 8 + gp) * LDS_STRIDE + k0 + tq;
                bfr[ni][0] = __float_as_uint(bp[0]);
                bfr[ni][1] = __float_as_uint(bp[4]);
            }
            #pragma unroll
            for (int mi = 0; mi < 2; mi++)
                #pragma unroll
                for (int ni = 0; ni < 4; ni++)
                    mma_tf32(acc[mi][ni], afr[mi], bfr[ni]);
        }
        __syncthreads();   // all reads of As done before overwrite

        // ---- epilogue 1: T = tf32(relu(y + b1)) -> As ------------------------
        #pragma unroll
        for (int mi = 0; mi < 2; mi++) {
            #pragma unroll
            for (int ni = 0; ni < 4; ni++) {
                int col = ng * 32 + ni * 8 + tq * 2;
                int r0  = mg * 32 + mi * 16 + gp;
                float t0 = acc[mi][ni][0] + sb1[col];
                float t1 = acc[mi][ni][1] + sb1[col + 1];
                float t2 = acc[mi][ni][2] + sb1[col];
                float t3 = acc[mi][ni][3] + sb1[col + 1];
                float2 v01 = make_float2(tf32r(t0 > 0.f ? t0 : 0.f), tf32r(t1 > 0.f ? t1 : 0.f));
                float2 v23 = make_float2(tf32r(t2 > 0.f ? t2 : 0.f), tf32r(t3 > 0.f ? t3 : 0.f));
                *(float2*)(As + r0 * LDS_STRIDE + col)       = v01;
                *(float2*)(As + (r0 + 8) * LDS_STRIDE + col) = v23;
                acc[mi][ni][0] = 0.f; acc[mi][ni][1] = 0.f;
                acc[mi][ni][2] = 0.f; acc[mi][ni][3] = 0.f;
            }
        }
        __syncthreads();

        // ---- GEMM 2: Y = T @ W2 ---------------------------------------------
        #pragma unroll
        for (int s = 0; s < 16; s++) {
            int k0 = s * 8;
            uint32_t afr[2][4], bfr[4][2];
            #pragma unroll
            for (int mi = 0; mi < 2; mi++) {
                const float* ap = As + (mg * 32 + mi * 16 + gp) * LDS_STRIDE + k0 + tq;
                afr[mi][0] = __float_as_uint(ap[0]);
                afr[mi][1] = __float_as_uint(ap[8 * LDS_STRIDE]);
                afr[mi][2] = __float_as_uint(ap[4]);
                afr[mi][3] = __float_as_uint(ap[8 * LDS_STRIDE + 4]);
            }
            #pragma unroll
            for (int ni = 0; ni < 4; ni++) {
                const float* bp = B2s + (ng * 32 + ni * 8 + gp) * LDS_STRIDE + k0 + tq;
                bfr[ni][0] = __float_as_uint(bp[0]);
                bfr[ni][1] = __float_as_uint(bp[4]);
            }
            #pragma unroll
            for (int mi = 0; mi < 2; mi++)
                #pragma unroll
                for (int ni = 0; ni < 4; ni++)
                    mma_tf32(acc[mi][ni], afr[mi], bfr[ni]);
        }

        // ---- epilogue 2: bias + BN + relu -> gmem (or pool via RED) ----------
        #pragma unroll
        for (int mi = 0; mi < 2; mi++) {
            #pragma unroll
            for (int ni = 0; ni < 4; ni++) {
                int col = ng * 32 + ni * 8 + tq * 2;
                int r0  = mg * 32 + mi * 16 + gp;
                int gr0 = row0 + r0;
                int gr1 = gr0 + 8;
                float kk0 = skk[col], kk1 = skk[col + 1];
                float t;
                float2 v;
                if (gr0 < nNodes) {
                    t = (acc[mi][ni][0] + sb2[col]     - smm[col])     * kk0 + scc[col];
                    v.x = t > 0.f ? t : 0.f;
                    t = (acc[mi][ni][1] + sb2[col + 1] - smm[col + 1]) * kk1 + scc[col + 1];
                    v.y = t > 0.f ? t : 0.f;
                    if (poolMode) red_add_v2(pool + (size_t)batch[gr0] * D + col, v.x, v.y);
                    else          *(float2*)(xout + (size_t)gr0 * D + col) = v;
                }
                if (gr1 < nNodes) {
                    t = (acc[mi][ni][2] + sb2[col]     - smm[col])     * kk0 + scc[col];
                    v.x = t > 0.f ? t : 0.f;
                    t = (acc[mi][ni][3] + sb2[col + 1] - smm[col + 1]) * kk1 + scc[col + 1];
                    v.y = t > 0.f ? t : 0.f;
                    if (poolMode) red_add_v2(pool + (size_t)batch[gr1] * D + col, v.x, v.y);
                    else          *(float2*)(xout + (size_t)gr1 * D + col) = v;
                }
            }
        }
        __syncthreads();   // protect As before next tile's load
    }
}

// ---------------- head --------------------------------------------------------
#define HID 64
#define NCLS 12
__global__ void head_kernel(const float* __restrict__ pool,
                            const float* __restrict__ Wh1, const float* __restrict__ bh1,
                            const float* __restrict__ Wh2, const float* __restrict__ bh2,
                            float* __restrict__ out, int nGraphs) {
    __shared__ float sg[D];
    __shared__ float sh1[HID];
    int g = blockIdx.x;
    if (g >= nGraphs) return;
    int tid = threadIdx.x;
    sg[tid]       = pool[g * D + tid];
    sg[tid + HID] = pool[g * D + tid + HID];
    __syncthreads();
    float a = bh1[tid];
    #pragma unroll 4
    for (int k = 0; k < D; k++) a += sg[k] * Wh1[k * HID + tid];
    sh1[tid] = a > 0.f ? a : 0.f;
    __syncthreads();
    if (tid < NCLS) {
        float o = bh2[tid];
        #pragma unroll
        for (int k = 0; k < HID; k++) o += sh1[k] * Wh2[k * NCLS + tid];
        out[g * NCLS + tid] = 1.f / (1.f + expf(-o));
    }
}

// ---------------- launcher ---------------------------------------------------
extern "C" void kernel_launch(void* const* d_in, const int* in_sizes, int n_in,
                              void* d_out, int out_size) {
    const float* x     = (const float*)d_in[0];
    const int*   ei    = (const int*)d_in[1];
    const int*   batch = (const int*)d_in[2];
    const float* W1    = (const float*)d_in[3];
    const float* b1    = (const float*)d_in[4];
    const float* W2    = (const float*)d_in[5];
    const float* b2    = (const float*)d_in[6];
    const float* bns   = (const float*)d_in[7];
    const float* bnb   = (const float*)d_in[8];
    const float* bnm   = (const float*)d_in[9];
    const float* bnv   = (const float*)d_in[10];
    const float* Wh1   = (const float*)d_in[11];
    const float* bh1   = (const float*)d_in[12];
    const float* Wh2   = (const float*)d_in[13];
    const float* bh2   = (const float*)d_in[14];
    float* out = (float*)d_out;

    int nNodes  = in_sizes[0] / D;
    int nEdges  = in_sizes[1] / 2;
    int nGraphs = out_size / NCLS;

    const int* src = ei;
    const int* dst = ei + nEdges;

    float *h, *x1, *x2, *pool, *w1t, *w2t;
    int *cnt, *rowptr, *tick, *csrsrc;
    cudaGetSymbolAddress((void**)&h,      g_h);
    cudaGetSymbolAddress((void**)&x1,     g_x1);
    cudaGetSymbolAddress((void**)&x2,     g_x2);
    cudaGetSymbolAddress((void**)&pool,   g_pool);
    cudaGetSymbolAddress((void**)&w1t,    g_w1t);
    cudaGetSymbolAddress((void**)&w2t,    g_w2t);
    cudaGetSymbolAddress((void**)&cnt,    g_cnt);
    cudaGetSymbolAddress((void**)&rowptr, g_rowptr);
    cudaGetSymbolAddress((void**)&tick,   g_tick);
    cudaGetSymbolAddress((void**)&csrsrc, g_csrsrc);

    cudaFuncSetAttribute(mlp_mma_kernel, cudaFuncAttributeMaxDynamicSharedMemorySize,
                         SMEM_TOTAL_MLP);

    // weight prep + CSR build (once per launch)
    wprep_kernel<<<dim3(4, 4, 6), dim3(32, 8)>>>(W1, W2, w1t, w2t);
    cudaMemsetAsync(cnt, 0, (size_t)nNodes * sizeof(int));
    int eb = (nEdges + 255) / 256;
    hist_kernel<<<eb, 256>>>(dst, cnt, tick, nEdges);
    scan_kernel<<<1, 1024>>>(cnt, rowptr, nNodes);
    fill_kernel<<<eb, 256>>>(src, dst, rowptr, tick, csrsrc, nEdges);

    cudaMemsetAsync(pool, 0, (size_t)nGraphs * D * sizeof(float));

    int gatherBlocks = (nNodes * 32 + 255) / 256;
    int nTiles = (nNodes + TILE_M - 1) / TILE_M;
    int mlpGrid = nTiles < 148 ? nTiles : 148;

    const float* xs[3] = { x, x1, x2 };
    float*       xd[3] = { x1, x2, x1 };

    for (int l = 0; l < 3; l++) {
        gather_kernel<<<gatherBlocks, 256>>>(xs[l], rowptr, csrsrc, h, nNodes);
        mlp_mma_kernel<<<mlpGrid, 512, SMEM_TOTAL_MLP>>>(
            h,
            w1t + l * D * D, b1 + l * D,
            w2t + l * D * D, b2 + l * D,
            bns + l * D, bnb + l * D, bnm + l * D, bnv + l * D,
            xd[l], batch, pool, (l == 2) ? 1 : 0, nNodes);
    }

    head_kernel<<<nGraphs, HID>>>(pool, Wh1, bh1, Wh2, bh2, out, nGraphs);
}

// round 13
// speedup vs baseline: 1.0898x; 1.0041x over previous
#include <cuda_runtime.h>
#include <cuda_bf16.h>
#include <math.h>
#include <cstdint>

#define D 128
#define MAX_NODES 50000
#define MAX_EDGES 640000
#define MAX_GRAPHS 500
#define BN_EPS 1e-5f

// ---------------- scratch ----------------------------------------------------
__device__ float g_h   [MAX_NODES * D];
__device__ float g_x1  [MAX_NODES * D];
__device__ float g_x2  [MAX_NODES * D];
__device__ float g_pool[MAX_GRAPHS * D];
__device__ float g_w1p [3 * D * D];   // W1^T in fragment-permuted order
__device__ float g_w2p [3 * D * D];
__device__ int   g_cnt [MAX_NODES];
__device__ int   g_rowptr[MAX_NODES + 1];
__device__ int   g_tick[MAX_EDGES];
__device__ int   g_csrsrc[MAX_EDGES];

// ---------------- helpers ----------------------------------------------------
__device__ __forceinline__ float tf32r(float v) {
    float o;
    asm("cvt.rna.tf32.f32 %0, %1;" : "=f"(o) : "f"(v));
    return o;
}
__device__ __forceinline__ void red_add_v2(float* p, float a, float b) {
    asm volatile("red.global.add.v2.f32 [%0], {%1,%2};"
                 :: "l"(p), "f"(a), "f"(b) : "memory");
}
__device__ __forceinline__ void mma_tf32(float* d, const uint32_t* a, uint32_t b0, uint32_t b1) {
    asm volatile(
        "mma.sync.aligned.m16n8k8.row.col.f32.tf32.tf32.f32 "
        "{%0,%1,%2,%3}, {%4,%5,%6,%7}, {%8,%9}, {%0,%1,%2,%3};"
        : "+f"(d[0]), "+f"(d[1]), "+f"(d[2]), "+f"(d[3])
        : "r"(a[0]), "r"(a[1]), "r"(a[2]), "r"(a[3]), "r"(b0), "r"(b1));
}
// A-tile fragment-permuted block base (float index)
__device__ __forceinline__ int ablk(int mb, int s, int mi) {
    return mb * 4096 + s * 256 + mi * 128;
}

// ---------------- CSR build ---------------------------------------------------
__global__ void hist_kernel(const int* __restrict__ dst, int* __restrict__ cnt,
                            int* __restrict__ tick, int nEdges) {
    int e = blockIdx.x * blockDim.x + threadIdx.x;
    if (e < nEdges) tick[e] = atomicAdd(&cnt[dst[e]], 1);
}

__global__ void scan_kernel(const int* __restrict__ cnt, int* __restrict__ rowptr, int n) {
    __shared__ int part[1024];
    int tid = threadIdx.x;
    int chunk = (n + 1023) / 1024;
    int beg = tid * chunk;
    int end = beg + chunk < n ? beg + chunk : n;
    int s = 0;
    for (int i = beg; i < end; i++) s += cnt[i];
    part[tid] = s;
    __syncthreads();
    for (int off = 1; off < 1024; off <<= 1) {
        int v = (tid >= off) ? part[tid - off] : 0;
        __syncthreads();
        part[tid] += v;
        __syncthreads();
    }
    int base = (tid > 0) ? part[tid - 1] : 0;
    for (int i = beg; i < end; i++) {
        rowptr[i] = base;
        base += cnt[i];
    }
    if (tid == 1023) rowptr[n] = part[1023];
}

__global__ void fill_kernel(const int* __restrict__ src, const int* __restrict__ dst,
                            const int* __restrict__ rowptr, const int* __restrict__ tick,
                            int* __restrict__ csrsrc, int nEdges) {
    int e = blockIdx.x * blockDim.x + threadIdx.x;
    if (e < nEdges) csrsrc[rowptr[dst[e]] + tick[e]] = src[e];
}

// ---------------- weight prep: transpose + tf32 round + fragment-permute -----
// out layout: [nb(4)][ni(4)][sp(8)][t(32)][4] where the 4 floats are
// {s=2sp:B[n][k0+tq], B[n][k0+tq+4], s=2sp+1: same} for thread t=(gp,tq)
__global__ void wprep_kernel(const float* __restrict__ W1, const float* __restrict__ W2,
                             float* __restrict__ w1p, float* __restrict__ w2p) {
    int idx = blockIdx.x * blockDim.x + threadIdx.x;
    if (idx >= 6 * D * D) return;
    int z   = idx >> 14;           // 0..5
    int rem = idx & 16383;
    int k   = rem >> 7;            // 0..127
    int n   = rem & 127;
    const float* W = (z < 3) ? (W1 + z * D * D) : (W2 + (z - 3) * D * D);
    float*       o = (z < 3) ? (w1p + z * D * D) : (w2p + (z - 3) * D * D);
    float val = tf32r(W[k * D + n]);   // W is [k][n]; operand B[n][k]
    int nb = n >> 5, nn = n & 31, ni = nn >> 3, gp = nn & 7;
    int s = k >> 3, sp = s >> 1, so = s & 1, kq = k & 7, tq = kq & 3, hi = kq >> 2;
    int addr = (((nb * 4 + ni) * 8 + sp) * 32 + gp * 4 + tq) * 4 + so * 2 + hi;
    o[addr] = val;
}

// ---------------- gather: h[i] = tf32r( x[i] + sum_{e in CSR(i)} x[src] ) -----
__global__ __launch_bounds__(256)
void gather_kernel(const float* __restrict__ x,
                   const int* __restrict__ rowptr,
                   const int* __restrict__ csrsrc,
                   float* __restrict__ h, int nNodes) {
    int gid  = blockIdx.x * blockDim.x + threadIdx.x;
    int node = gid >> 5;
    int lane = gid & 31;
    if (node >= nNodes) return;
    const float4* x4 = (const float4*)x;
    float4 a0 = x4[(size_t)node * 32 + lane];
    float4 a1 = make_float4(0.f, 0.f, 0.f, 0.f);
    float4 a2 = make_float4(0.f, 0.f, 0.f, 0.f);
    float4 a3 = make_float4(0.f, 0.f, 0.f, 0.f);
    int beg = rowptr[node];
    int end = rowptr[node + 1];
    int e = beg;
    for (; e + 3 < end; e += 4) {
        int s0 = csrsrc[e], s1 = csrsrc[e + 1], s2 = csrsrc[e + 2], s3 = csrsrc[e + 3];
        float4 v0 = x4[(size_t)s0 * 32 + lane];
        float4 v1 = x4[(size_t)s1 * 32 + lane];
        float4 v2 = x4[(size_t)s2 * 32 + lane];
        float4 v3 = x4[(size_t)s3 * 32 + lane];
        a0.x += v0.x; a0.y += v0.y; a0.z += v0.z; a0.w += v0.w;
        a1.x += v1.x; a1.y += v1.y; a1.z += v1.z; a1.w += v1.w;
        a2.x += v2.x; a2.y += v2.y; a2.z += v2.z; a2.w += v2.w;
        a3.x += v3.x; a3.y += v3.y; a3.z += v3.z; a3.w += v3.w;
    }
    for (; e < end; e++) {
        int s0 = csrsrc[e];
        float4 v0 = x4[(size_t)s0 * 32 + lane];
        a0.x += v0.x; a0.y += v0.y; a0.z += v0.z; a0.w += v0.w;
    }
    float4 hv;
    hv.x = tf32r((a0.x + a1.x) + (a2.x + a3.x));
    hv.y = tf32r((a0.y + a1.y) + (a2.y + a3.y));
    hv.z = tf32r((a0.z + a1.z) + (a2.z + a3.z));
    hv.w = tf32r((a0.w + a1.w) + (a2.w + a3.w));
    ((float4*)h)[(size_t)node * 32 + lane] = hv;
}

// ---------------- persistent fused MLP, fragment-permuted smem ----------------
#define TILE_M 128
#define AP_FLOATS (128 * 128)    // 16384, fragment-permuted A/T tile
#define BP_FLOATS (128 * 128)    // per weight matrix
#define P_FLOATS (5 * 128)
#define SMEM_TOTAL_MLP ((AP_FLOATS + 2 * BP_FLOATS + P_FLOATS) * 4)  // ~194.5 KB

__global__ __launch_bounds__(512, 1)
void mlp_mma_kernel(const float* __restrict__ hin,
                    const float* __restrict__ w1p, const float* __restrict__ b1,
                    const float* __restrict__ w2p, const float* __restrict__ b2,
                    const float* __restrict__ bns, const float* __restrict__ bnb,
                    const float* __restrict__ bnm, const float* __restrict__ bnv,
                    float* __restrict__ xout,
                    const int* __restrict__ batch, float* __restrict__ pool,
                    int poolMode, int nNodes) {
    extern __shared__ float smem[];
    float* As  = smem;                     // fragment-permuted A / T tile
    float* B1s = smem + AP_FLOATS;
    float* B2s = B1s + BP_FLOATS;
    float* sb1 = B2s + BP_FLOATS;
    float* sb2 = sb1 + 128;
    float* skk = sb2 + 128;
    float* smm = skk + 128;
    float* scc = smm + 128;

    int tid  = threadIdx.x;
    int wid  = tid >> 5;
    int lane = tid & 31;
    int mg   = wid >> 2;        // 0..3
    int ng   = wid & 3;         // 0..3
    int gp   = lane >> 2;       // 0..7
    int tq   = lane & 3;        // 0..3

    if (tid < 128) {
        sb1[tid] = b1[tid];
        sb2[tid] = b2[tid];
        skk[tid] = bns[tid] * rsqrtf(bnv[tid] + BN_EPS);
        smm[tid] = bnm[tid];
        scc[tid] = bnb[tid];
    }

    // ---- load permuted weights ONCE (straight copy) --------------------------
    {
        const float4* w14 = (const float4*)w1p;
        const float4* w24 = (const float4*)w2p;
        #pragma unroll
        for (int it = 0; it < 8; it++) {
            int i = tid + it * 512;          // 4096 float4
            ((float4*)B1s)[i] = w14[i];
            ((float4*)B2s)[i] = w24[i];
        }
    }
    __syncthreads();

    const float4* h4 = (const float4*)hin;
    int nTiles = (nNodes + TILE_M - 1) / TILE_M;

    for (int tile = blockIdx.x; tile < nTiles; tile += gridDim.x) {
        int row0 = tile * TILE_M;

        // ---- load A tile into fragment-permuted layout -----------------------
        #pragma unroll
        for (int it = 0; it < 8; it++) {
            int i = tid + it * 512;          // 128 rows x 32 float4
            int row = i >> 5, c4 = i & 31;
            int gr = row0 + row;
            float4 hv = make_float4(0.f, 0.f, 0.f, 0.f);
            if (gr < nNodes) hv = h4[(size_t)gr * 32 + c4];
            int mb = row >> 5, rr = row & 31;
            int mi = rr >> 4, gpw = rr & 7, half = (rr >> 3) & 1;
            int s = c4 >> 1, hi = c4 & 1;
            int e = half + 2 * hi;
            int swz = (s & 7) << 2;
            float* p = As + ablk(mb, s, mi);
            p[(gpw * 16 + 0  + e) ^ swz] = hv.x;
            p[(gpw * 16 + 4  + e) ^ swz] = hv.y;
            p[(gpw * 16 + 8  + e) ^ swz] = hv.z;
            p[(gpw * 16 + 12 + e) ^ swz] = hv.w;
        }
        __syncthreads();

        float acc[2][4][4];
        #pragma unroll
        for (int mi = 0; mi < 2; mi++)
            #pragma unroll
            for (int ni = 0; ni < 4; ni++)
                #pragma unroll
                for (int c = 0; c < 4; c++) acc[mi][ni][c] = 0.f;

        // ---- GEMM 1: T = H @ W1 ---------------------------------------------
        #pragma unroll
        for (int sp = 0; sp < 8; sp++) {
            int s0 = 2 * sp, s1 = 2 * sp + 1;
            float4 a0[2], a1[2], bb[4];
            #pragma unroll
            for (int mi = 0; mi < 2; mi++) {
                a0[mi] = *(const float4*)(As + ablk(mg, s0, mi) + (((lane * 4) ^ ((s0 & 7) << 2))));
                a1[mi] = *(const float4*)(As + ablk(mg, s1, mi) + (((lane * 4) ^ ((s1 & 7) << 2))));
            }
            #pragma unroll
            for (int ni = 0; ni < 4; ni++)
                bb[ni] = *(const float4*)(B1s + (((ng * 4 + ni) * 8 + sp) * 32 + lane) * 4);
            #pragma unroll
            for (int mi = 0; mi < 2; mi++)
                #pragma unroll
                for (int ni = 0; ni < 4; ni++)
                    mma_tf32(acc[mi][ni], (const uint32_t*)&a0[mi],
                             __float_as_uint(bb[ni].x), __float_as_uint(bb[ni].y));
            #pragma unroll
            for (int mi = 0; mi < 2; mi++)
                #pragma unroll
                for (int ni = 0; ni < 4; ni++)
                    mma_tf32(acc[mi][ni], (const uint32_t*)&a1[mi],
                             __float_as_uint(bb[ni].z), __float_as_uint(bb[ni].w));
        }
        __syncthreads();   // all reads of As done

        // ---- epilogue 1: T = tf32(relu(y + b1)) -> As (fragment-permuted) ----
        #pragma unroll
        for (int mi = 0; mi < 2; mi++) {
            #pragma unroll
            for (int ni = 0; ni < 4; ni++) {
                int s   = ng * 4 + ni;
                int swz = (s & 7) << 2;
                float* p = As + ablk(mg, s, mi);
                int colbase = ng * 32 + ni * 8 + tq * 2;
                #pragma unroll
                for (int c = 0; c < 4; c++) {
                    int half = c >> 1;
                    int kq   = 2 * tq + (c & 1);
                    int t    = gp * 4 + (kq & 3);
                    int e    = half + 2 * (kq >> 2);
                    float v  = acc[mi][ni][c] + sb1[colbase + (c & 1)];
                    p[(t * 4 + e) ^ swz] = tf32r(v > 0.f ? v : 0.f);
                    acc[mi][ni][c] = 0.f;
                }
            }
        }
        __syncthreads();

        // ---- GEMM 2: Y = T @ W2 ---------------------------------------------
        #pragma unroll
        for (int sp = 0; sp < 8; sp++) {
            int s0 = 2 * sp, s1 = 2 * sp + 1;
            float4 a0[2], a1[2], bb[4];
            #pragma unroll
            for (int mi = 0; mi < 2; mi++) {
                a0[mi] = *(const float4*)(As + ablk(mg, s0, mi) + (((lane * 4) ^ ((s0 & 7) << 2))));
                a1[mi] = *(const float4*)(As + ablk(mg, s1, mi) + (((lane * 4) ^ ((s1 & 7) << 2))));
            }
            #pragma unroll
            for (int ni = 0; ni < 4; ni++)
                bb[ni] = *(const float4*)(B2s + (((ng * 4 + ni) * 8 + sp) * 32 + lane) * 4);
            #pragma unroll
            for (int mi = 0; mi < 2; mi++)
                #pragma unroll
                for (int ni = 0; ni < 4; ni++)
                    mma_tf32(acc[mi][ni], (const uint32_t*)&a0[mi],
                             __float_as_uint(bb[ni].x), __float_as_uint(bb[ni].y));
            #pragma unroll
            for (int mi = 0; mi < 2; mi++)
                #pragma unroll
                for (int ni = 0; ni < 4; ni++)
                    mma_tf32(acc[mi][ni], (const uint32_t*)&a1[mi],
                             __float_as_uint(bb[ni].z), __float_as_uint(bb[ni].w));
        }

        // ---- epilogue 2: bias + BN + relu -> gmem (or pool via RED) ----------
        #pragma unroll
        for (int mi = 0; mi < 2; mi++) {
            #pragma unroll
            for (int ni = 0; ni < 4; ni++) {
                int col = ng * 32 + ni * 8 + tq * 2;
                int r0  = mg * 32 + mi * 16 + gp;
                int gr0 = row0 + r0;
                int gr1 = gr0 + 8;
                float kk0 = skk[col], kk1 = skk[col + 1];
                float t;
                float2 v;
                if (gr0 < nNodes) {
                    t = (acc[mi][ni][0] + sb2[col]     - smm[col])     * kk0 + scc[col];
                    v.x = t > 0.f ? t : 0.f;
                    t = (acc[mi][ni][1] + sb2[col + 1] - smm[col + 1]) * kk1 + scc[col + 1];
                    v.y = t > 0.f ? t : 0.f;
                    if (poolMode) red_add_v2(pool + (size_t)batch[gr0] * D + col, v.x, v.y);
                    else          *(float2*)(xout + (size_t)gr0 * D + col) = v;
                }
                if (gr1 < nNodes) {
                    t = (acc[mi][ni][2] + sb2[col]     - smm[col])     * kk0 + scc[col];
                    v.x = t > 0.f ? t : 0.f;
                    t = (acc[mi][ni][3] + sb2[col + 1] - smm[col + 1]) * kk1 + scc[col + 1];
                    v.y = t > 0.f ? t : 0.f;
                    if (poolMode) red_add_v2(pool + (size_t)batch[gr1] * D + col, v.x, v.y);
                    else          *(float2*)(xout + (size_t)gr1 * D + col) = v;
                }
            }
        }
        __syncthreads();   // protect As before next tile's load
    }
}

// ---------------- head --------------------------------------------------------
#define HID 64
#define NCLS 12
__global__ void head_kernel(const float* __restrict__ pool,
                            const float* __restrict__ Wh1, const float* __restrict__ bh1,
                            const float* __restrict__ Wh2, const float* __restrict__ bh2,
                            float* __restrict__ out, int nGraphs) {
    __shared__ float sg[D];
    __shared__ float sh1[HID];
    int g = blockIdx.x;
    if (g >= nGraphs) return;
    int tid = threadIdx.x;
    sg[tid]       = pool[g * D + tid];
    sg[tid + HID] = pool[g * D + tid + HID];
    __syncthreads();
    float a = bh1[tid];
    #pragma unroll 4
    for (int k = 0; k < D; k++) a += sg[k] * Wh1[k * HID + tid];
    sh1[tid] = a > 0.f ? a : 0.f;
    __syncthreads();
    if (tid < NCLS) {
        float o = bh2[tid];
        #pragma unroll
        for (int k = 0; k < HID; k++) o += sh1[k] * Wh2[k * NCLS + tid];
        out[g * NCLS + tid] = 1.f / (1.f + expf(-o));
    }
}

// ---------------- launcher ---------------------------------------------------
extern "C" void kernel_launch(void* const* d_in, const int* in_sizes, int n_in,
                              void* d_out, int out_size) {
    const float* x     = (const float*)d_in[0];
    const int*   ei    = (const int*)d_in[1];
    const int*   batch = (const int*)d_in[2];
    const float* W1    = (const float*)d_in[3];
    const float* b1    = (const float*)d_in[4];
    const float* W2    = (const float*)d_in[5];
    const float* b2    = (const float*)d_in[6];
    const float* bns   = (const float*)d_in[7];
    const float* bnb   = (const float*)d_in[8];
    const float* bnm   = (const float*)d_in[9];
    const float* bnv   = (const float*)d_in[10];
    const float* Wh1   = (const float*)d_in[11];
    const float* bh1   = (const float*)d_in[12];
    const float* Wh2   = (const float*)d_in[13];
    const float* bh2   = (const float*)d_in[14];
    float* out = (float*)d_out;

    int nNodes  = in_sizes[0] / D;
    int nEdges  = in_sizes[1] / 2;
    int nGraphs = out_size / NCLS;

    const int* src = ei;
    const int* dst = ei + nEdges;

    float *h, *x1, *x2, *pool, *w1p, *w2p;
    int *cnt, *rowptr, *tick, *csrsrc;
    cudaGetSymbolAddress((void**)&h,      g_h);
    cudaGetSymbolAddress((void**)&x1,     g_x1);
    cudaGetSymbolAddress((void**)&x2,     g_x2);
    cudaGetSymbolAddress((void**)&pool,   g_pool);
    cudaGetSymbolAddress((void**)&w1p,    g_w1p);
    cudaGetSymbolAddress((void**)&w2p,    g_w2p);
    cudaGetSymbolAddress((void**)&cnt,    g_cnt);
    cudaGetSymbolAddress((void**)&rowptr, g_rowptr);
    cudaGetSymbolAddress((void**)&tick,   g_tick);
    cudaGetSymbolAddress((void**)&csrsrc, g_csrsrc);

    cudaFuncSetAttribute(mlp_mma_kernel, cudaFuncAttributeMaxDynamicSharedMemorySize,
                         SMEM_TOTAL_MLP);

    // weight prep + CSR build (once per launch)
    wprep_kernel<<<(6 * D * D + 255) / 256, 256>>>(W1, W2, w1p, w2p);
    cudaMemsetAsync(cnt, 0, (size_t)nNodes * sizeof(int));
    int eb = (nEdges + 255) / 256;
    hist_kernel<<<eb, 256>>>(dst, cnt, tick, nEdges);
    scan_kernel<<<1, 1024>>>(cnt, rowptr, nNodes);
    fill_kernel<<<eb, 256>>>(src, dst, rowptr, tick, csrsrc, nEdges);

    cudaMemsetAsync(pool, 0, (size_t)nGraphs * D * sizeof(float));

    int gatherBlocks = (nNodes * 32 + 255) / 256;
    int nTiles = (nNodes + TILE_M - 1) / TILE_M;
    int mlpGrid = nTiles < 148 ? nTiles : 148;

    const float* xs[3] = { x, x1, x2 };
    float*       xd[3] = { x1, x2, x1 };

    for (int l = 0; l < 3; l++) {
        gather_kernel<<<gatherBlocks, 256>>>(xs[l], rowptr, csrsrc, h, nNodes);
        mlp_mma_kernel<<<mlpGrid, 512, SMEM_TOTAL_MLP>>>(
            h,
            w1p + l * D * D, b1 + l * D,
            w2p + l * D * D, b2 + l * D,
            bns + l * D, bnb + l * D, bnm + l * D, bnv + l * D,
            xd[l], batch, pool, (l == 2) ? 1 : 0, nNodes);
    }

    head_kernel<<<nGraphs, HID>>>(pool, Wh1, bh1, Wh2, bh2, out, nGraphs);
}

// round 14
// speedup vs baseline: 1.2820x; 1.1764x over previous
#include <cuda_runtime.h>
#include <cuda_fp16.h>
#include <math.h>
#include <cstdint>

#define D 128
#define MAX_NODES 50000
#define MAX_EDGES 640000
#define MAX_GRAPHS 500
#define BN_EPS 1e-5f

// ---------------- scratch ----------------------------------------------------
__device__ __half g_h  [MAX_NODES * D];     // gathered input, fp16
__device__ float  g_x1 [MAX_NODES * D];
__device__ float  g_x2 [MAX_NODES * D];
__device__ float  g_pool[MAX_GRAPHS * D];
__device__ __half g_w1h[3 * D * D];         // W1^T [n][k] fp16
__device__ __half g_w2h[3 * D * D];
__device__ int    g_cnt [MAX_NODES];
__device__ int    g_rowptr[MAX_NODES + 1];
__device__ int    g_tick[MAX_EDGES];
__device__ int    g_csrsrc[MAX_EDGES];

// ---------------- helpers ----------------------------------------------------
__device__ __forceinline__ void red_add_v2(float* p, float a, float b) {
    asm volatile("red.global.add.v2.f32 [%0], {%1,%2};"
                 :: "l"(p), "f"(a), "f"(b) : "memory");
}
// mma m16n8k16 fp16 inputs, fp32 accumulate
__device__ __forceinline__ void mma_f16(float* d, const uint32_t* a, uint32_t b0, uint32_t b1) {
    asm volatile(
        "mma.sync.aligned.m16n8k16.row.col.f32.f16.f16.f32 "
        "{%0,%1,%2,%3}, {%4,%5,%6,%7}, {%8,%9}, {%0,%1,%2,%3};"
        : "+f"(d[0]), "+f"(d[1]), "+f"(d[2]), "+f"(d[3])
        : "r"(a[0]), "r"(a[1]), "r"(a[2]), "r"(a[3]), "r"(b0), "r"(b1));
}

// ---------------- CSR build ---------------------------------------------------
__global__ void hist_kernel(const int* __restrict__ dst, int* __restrict__ cnt,
                            int* __restrict__ tick, int nEdges) {
    int e = blockIdx.x * blockDim.x + threadIdx.x;
    if (e < nEdges) tick[e] = atomicAdd(&cnt[dst[e]], 1);
}

__global__ void scan_kernel(const int* __restrict__ cnt, int* __restrict__ rowptr, int n) {
    __shared__ int part[1024];
    int tid = threadIdx.x;
    int chunk = (n + 1023) / 1024;
    int beg = tid * chunk;
    int end = beg + chunk < n ? beg + chunk : n;
    int s = 0;
    for (int i = beg; i < end; i++) s += cnt[i];
    part[tid] = s;
    __syncthreads();
    for (int off = 1; off < 1024; off <<= 1) {
        int v = (tid >= off) ? part[tid - off] : 0;
        __syncthreads();
        part[tid] += v;
        __syncthreads();
    }
    int base = (tid > 0) ? part[tid - 1] : 0;
    for (int i = beg; i < end; i++) {
        rowptr[i] = base;
        base += cnt[i];
    }
    if (tid == 1023) rowptr[n] = part[1023];
}

__global__ void fill_kernel(const int* __restrict__ src, const int* __restrict__ dst,
                            const int* __restrict__ rowptr, const int* __restrict__ tick,
                            int* __restrict__ csrsrc, int nEdges) {
    int e = blockIdx.x * blockDim.x + threadIdx.x;
    if (e < nEdges) csrsrc[rowptr[dst[e]] + tick[e]] = src[e];
}

// ---------------- weight prep: transpose + fp16 ------------------------------
__global__ void wprep_kernel(const float* __restrict__ W1, const float* __restrict__ W2,
                             __half* __restrict__ w1h, __half* __restrict__ w2h) {
    int idx = blockIdx.x * blockDim.x + threadIdx.x;
    if (idx >= 6 * D * D) return;
    int z   = idx >> 14;
    int rem = idx & 16383;
    int k   = rem >> 7;
    int n   = rem & 127;
    const float* W = (z < 3) ? (W1 + z * D * D) : (W2 + (z - 3) * D * D);
    __half*      o = (z < 3) ? (w1h + z * D * D) : (w2h + (z - 3) * D * D);
    o[n * D + k] = __float2half_rn(W[k * D + n]);
}

// ---------------- gather: h[i] = fp16( x[i] + sum_{e in CSR(i)} x[src] ) ------
__global__ __launch_bounds__(256)
void gather_kernel(const float* __restrict__ x,
                   const int* __restrict__ rowptr,
                   const int* __restrict__ csrsrc,
                   __half* __restrict__ h, int nNodes) {
    int gid  = blockIdx.x * blockDim.x + threadIdx.x;
    int node = gid >> 5;
    int lane = gid & 31;
    if (node >= nNodes) return;
    const float4* x4 = (const float4*)x;
    float4 a0 = x4[(size_t)node * 32 + lane];
    float4 a1 = make_float4(0.f, 0.f, 0.f, 0.f);
    float4 a2 = make_float4(0.f, 0.f, 0.f, 0.f);
    float4 a3 = make_float4(0.f, 0.f, 0.f, 0.f);
    int beg = rowptr[node];
    int end = rowptr[node + 1];
    int e = beg;
    for (; e + 3 < end; e += 4) {
        int s0 = csrsrc[e], s1 = csrsrc[e + 1], s2 = csrsrc[e + 2], s3 = csrsrc[e + 3];
        float4 v0 = x4[(size_t)s0 * 32 + lane];
        float4 v1 = x4[(size_t)s1 * 32 + lane];
        float4 v2 = x4[(size_t)s2 * 32 + lane];
        float4 v3 = x4[(size_t)s3 * 32 + lane];
        a0.x += v0.x; a0.y += v0.y; a0.z += v0.z; a0.w += v0.w;
        a1.x += v1.x; a1.y += v1.y; a1.z += v1.z; a1.w += v1.w;
        a2.x += v2.x; a2.y += v2.y; a2.z += v2.z; a2.w += v2.w;
        a3.x += v3.x; a3.y += v3.y; a3.z += v3.z; a3.w += v3.w;
    }
    for (; e < end; e++) {
        int s0 = csrsrc[e];
        float4 v0 = x4[(size_t)s0 * 32 + lane];
        a0.x += v0.x; a0.y += v0.y; a0.z += v0.z; a0.w += v0.w;
    }
    float fx = (a0.x + a1.x) + (a2.x + a3.x);
    float fy = (a0.y + a1.y) + (a2.y + a3.y);
    float fz = (a0.z + a1.z) + (a2.z + a3.z);
    float fw = (a0.w + a1.w) + (a2.w + a3.w);
    __half2* h2 = (__half2*)h;
    h2[(size_t)node * 64 + lane * 2 + 0] = __floats2half2_rn(fx, fy);
    h2[(size_t)node * 64 + lane * 2 + 1] = __floats2half2_rn(fz, fw);
}

// ---------------- persistent fused MLP, fp16 m16n8k16 -------------------------
#define TILE_M 128
#define HSTRIDE 136                               // halves per row (pad 8)
#define TILE_HALVES (128 * HSTRIDE)               // 17408
#define P_FLOATS (5 * 128)
#define SMEM_TOTAL_MLP (3 * TILE_HALVES * 2 + P_FLOATS * 4)   // 107008 B

__global__ __launch_bounds__(512, 1)
void mlp_mma_kernel(const __half* __restrict__ hin,
                    const __half* __restrict__ w1h, const float* __restrict__ b1,
                    const __half* __restrict__ w2h, const float* __restrict__ b2,
                    const float* __restrict__ bns, const float* __restrict__ bnb,
                    const float* __restrict__ bnm, const float* __restrict__ bnv,
                    float* __restrict__ xout,
                    const int* __restrict__ batch, float* __restrict__ pool,
                    int poolMode, int nNodes) {
    extern __shared__ __half smemh[];
    __half* As  = smemh;                      // [128][136]
    __half* B1s = As + TILE_HALVES;
    __half* B2s = B1s + TILE_HALVES;
    float*  sb1 = (float*)(smemh + 3 * TILE_HALVES);
    float*  sb2 = sb1 + 128;
    float*  skk = sb2 + 128;
    float*  smm = skk + 128;
    float*  scc = smm + 128;

    int tid  = threadIdx.x;
    int wid  = tid >> 5;
    int lane = tid & 31;
    int mg   = wid >> 2;        // 0..3 rows mg*32..+31
    int ng   = wid & 3;         // 0..3 cols ng*32..+31
    int gp   = lane >> 2;       // 0..7
    int tq   = lane & 3;        // 0..3

    if (tid < 128) {
        sb1[tid] = b1[tid];
        sb2[tid] = b2[tid];
        skk[tid] = bns[tid] * rsqrtf(bnv[tid] + BN_EPS);
        smm[tid] = bnm[tid];
        scc[tid] = bnb[tid];
    }

    // ---- load both weight matrices ONCE (fp16 [n][k] -> padded smem) --------
    {
        const uint4* w14 = (const uint4*)w1h;   // 16B = 8 halves
        const uint4* w24 = (const uint4*)w2h;
        #pragma unroll
        for (int it = 0; it < 4; it++) {
            int i = tid + it * 512;             // 128 rows * 16 uint4 = 2048
            int row = i >> 4, c16 = i & 15;
            *(uint4*)(B1s + row * HSTRIDE + c16 * 8) = w14[i];
            *(uint4*)(B2s + row * HSTRIDE + c16 * 8) = w24[i];
        }
    }
    __syncthreads();

    const uint4* h4 = (const uint4*)hin;        // 16 uint4 per row
    int nTiles = (nNodes + TILE_M - 1) / TILE_M;

    for (int tile = blockIdx.x; tile < nTiles; tile += gridDim.x) {
        int row0 = tile * TILE_M;

        // ---- load A tile (fp16) ----------------------------------------------
        #pragma unroll
        for (int it = 0; it < 4; it++) {
            int i = tid + it * 512;
            int row = i >> 4, c16 = i & 15;
            int gr = row0 + row;
            uint4 hv = make_uint4(0u, 0u, 0u, 0u);
            if (gr < nNodes) hv = h4[(size_t)gr * 16 + c16];
            *(uint4*)(As + row * HSTRIDE + c16 * 8) = hv;
        }
        __syncthreads();

        float acc[2][4][4];
        #pragma unroll
        for (int mi = 0; mi < 2; mi++)
            #pragma unroll
            for (int ni = 0; ni < 4; ni++)
                #pragma unroll
                for (int c = 0; c < 4; c++) acc[mi][ni][c] = 0.f;

        // ---- GEMM 1: T = H @ W1 ---------------------------------------------
        #pragma unroll
        for (int s = 0; s < 8; s++) {
            int k0 = s * 16;
            uint32_t afr[2][4], bfr[4][2];
            #pragma unroll
            for (int mi = 0; mi < 2; mi++) {
                const __half* ap = As + (mg * 32 + mi * 16 + gp) * HSTRIDE + k0 + 2 * tq;
                afr[mi][0] = *(const uint32_t*)(ap);
                afr[mi][1] = *(const uint32_t*)(ap + 8 * HSTRIDE);
                afr[mi][2] = *(const uint32_t*)(ap + 8);
                afr[mi][3] = *(const uint32_t*)(ap + 8 * HSTRIDE + 8);
            }
            #pragma unroll
            for (int ni = 0; ni < 4; ni++) {
                const __half* bp = B1s + (ng * 32 + ni * 8 + gp) * HSTRIDE + k0 + 2 * tq;
                bfr[ni][0] = *(const uint32_t*)(bp);
                bfr[ni][1] = *(const uint32_t*)(bp + 8);
            }
            #pragma unroll
            for (int mi = 0; mi < 2; mi++)
                #pragma unroll
                for (int ni = 0; ni < 4; ni++)
                    mma_f16(acc[mi][ni], afr[mi], bfr[ni][0], bfr[ni][1]);
        }
        __syncthreads();   // all reads of As done before overwrite

        // ---- epilogue 1: T = fp16(relu(y + b1)) -> As ------------------------
        #pragma unroll
        for (int mi = 0; mi < 2; mi++) {
            #pragma unroll
            for (int ni = 0; ni < 4; ni++) {
                int col = ng * 32 + ni * 8 + 2 * tq;
                int r0  = mg * 32 + mi * 16 + gp;
                float t0 = acc[mi][ni][0] + sb1[col];
                float t1 = acc[mi][ni][1] + sb1[col + 1];
                float t2 = acc[mi][ni][2] + sb1[col];
                float t3 = acc[mi][ni][3] + sb1[col + 1];
                *(__half2*)(As + r0 * HSTRIDE + col) =
                    __floats2half2_rn(t0 > 0.f ? t0 : 0.f, t1 > 0.f ? t1 : 0.f);
                *(__half2*)(As + (r0 + 8) * HSTRIDE + col) =
                    __floats2half2_rn(t2 > 0.f ? t2 : 0.f, t3 > 0.f ? t3 : 0.f);
                acc[mi][ni][0] = 0.f; acc[mi][ni][1] = 0.f;
                acc[mi][ni][2] = 0.f; acc[mi][ni][3] = 0.f;
            }
        }
        __syncthreads();

        // ---- GEMM 2: Y = T @ W2 ---------------------------------------------
        #pragma unroll
        for (int s = 0; s < 8; s++) {
            int k0 = s * 16;
            uint32_t afr[2][4], bfr[4][2];
            #pragma unroll
            for (int mi = 0; mi < 2; mi++) {
                const __half* ap = As + (mg * 32 + mi * 16 + gp) * HSTRIDE + k0 + 2 * tq;
                afr[mi][0] = *(const uint32_t*)(ap);
                afr[mi][1] = *(const uint32_t*)(ap + 8 * HSTRIDE);
                afr[mi][2] = *(const uint32_t*)(ap + 8);
                afr[mi][3] = *(const uint32_t*)(ap + 8 * HSTRIDE + 8);
            }
            #pragma unroll
            for (int ni = 0; ni < 4; ni++) {
                const __half* bp = B2s + (ng * 32 + ni * 8 + gp) * HSTRIDE + k0 + 2 * tq;
                bfr[ni][0] = *(const uint32_t*)(bp);
                bfr[ni][1] = *(const uint32_t*)(bp + 8);
            }
            #pragma unroll
            for (int mi = 0; mi < 2; mi++)
                #pragma unroll
                for (int ni = 0; ni < 4; ni++)
                    mma_f16(acc[mi][ni], afr[mi], bfr[ni][0], bfr[ni][1]);
        }

        // ---- epilogue 2: bias + BN + relu -> gmem (or pool via RED) ----------
        #pragma unroll
        for (int mi = 0; mi < 2; mi++) {
            #pragma unroll
            for (int ni = 0; ni < 4; ni++) {
                int col = ng * 32 + ni * 8 + 2 * tq;
                int r0  = mg * 32 + mi * 16 + gp;
                int gr0 = row0 + r0;
                int gr1 = gr0 + 8;
                float kk0 = skk[col], kk1 = skk[col + 1];
                float t;
                float2 v;
                if (gr0 < nNodes) {
                    t = (acc[mi][ni][0] + sb2[col]     - smm[col])     * kk0 + scc[col];
                    v.x = t > 0.f ? t : 0.f;
                    t = (acc[mi][ni][1] + sb2[col + 1] - smm[col + 1]) * kk1 + scc[col + 1];
                    v.y = t > 0.f ? t : 0.f;
                    if (poolMode) red_add_v2(pool + (size_t)batch[gr0] * D + col, v.x, v.y);
                    else          *(float2*)(xout + (size_t)gr0 * D + col) = v;
                }
                if (gr1 < nNodes) {
                    t = (acc[mi][ni][2] + sb2[col]     - smm[col])     * kk0 + scc[col];
                    v.x = t > 0.f ? t : 0.f;
                    t = (acc[mi][ni][3] + sb2[col + 1] - smm[col + 1]) * kk1 + scc[col + 1];
                    v.y = t > 0.f ? t : 0.f;
                    if (poolMode) red_add_v2(pool + (size_t)batch[gr1] * D + col, v.x, v.y);
                    else          *(float2*)(xout + (size_t)gr1 * D + col) = v;
                }
            }
        }
        __syncthreads();   // protect As before next tile's load
    }
}

// ---------------- head --------------------------------------------------------
#define HID 64
#define NCLS 12
__global__ void head_kernel(const float* __restrict__ pool,
                            const float* __restrict__ Wh1, const float* __restrict__ bh1,
                            const float* __restrict__ Wh2, const float* __restrict__ bh2,
                            float* __restrict__ out, int nGraphs) {
    __shared__ float sg[D];
    __shared__ float sh1[HID];
    int g = blockIdx.x;
    if (g >= nGraphs) return;
    int tid = threadIdx.x;
    sg[tid]       = pool[g * D + tid];
    sg[tid + HID] = pool[g * D + tid + HID];
    __syncthreads();
    float a = bh1[tid];
    #pragma unroll 4
    for (int k = 0; k < D; k++) a += sg[k] * Wh1[k * HID + tid];
    sh1[tid] = a > 0.f ? a : 0.f;
    __syncthreads();
    if (tid < NCLS) {
        float o = bh2[tid];
        #pragma unroll
        for (int k = 0; k < HID; k++) o += sh1[k] * Wh2[k * NCLS + tid];
        out[g * NCLS + tid] = 1.f / (1.f + expf(-o));
    }
}

// ---------------- launcher ---------------------------------------------------
extern "C" void kernel_launch(void* const* d_in, const int* in_sizes, int n_in,
                              void* d_out, int out_size) {
    const float* x     = (const float*)d_in[0];
    const int*   ei    = (const int*)d_in[1];
    const int*   batch = (const int*)d_in[2];
    const float* W1    = (const float*)d_in[3];
    const float* b1    = (const float*)d_in[4];
    const float* W2    = (const float*)d_in[5];
    const float* b2    = (const float*)d_in[6];
    const float* bns   = (const float*)d_in[7];
    const float* bnb   = (const float*)d_in[8];
    const float* bnm   = (const float*)d_in[9];
    const float* bnv   = (const float*)d_in[10];
    const float* Wh1   = (const float*)d_in[11];
    const float* bh1   = (const float*)d_in[12];
    const float* Wh2   = (const float*)d_in[13];
    const float* bh2   = (const float*)d_in[14];
    float* out = (float*)d_out;

    int nNodes  = in_sizes[0] / D;
    int nEdges  = in_sizes[1] / 2;
    int nGraphs = out_size / NCLS;

    const int* src = ei;
    const int* dst = ei + nEdges;

    __half *h, *w1h, *w2h;
    float *x1, *x2, *pool;
    int *cnt, *rowptr, *tick, *csrsrc;
    cudaGetSymbolAddress((void**)&h,      g_h);
    cudaGetSymbolAddress((void**)&x1,     g_x1);
    cudaGetSymbolAddress((void**)&x2,     g_x2);
    cudaGetSymbolAddress((void**)&pool,   g_pool);
    cudaGetSymbolAddress((void**)&w1h,    g_w1h);
    cudaGetSymbolAddress((void**)&w2h,    g_w2h);
    cudaGetSymbolAddress((void**)&cnt,    g_cnt);
    cudaGetSymbolAddress((void**)&rowptr, g_rowptr);
    cudaGetSymbolAddress((void**)&tick,   g_tick);
    cudaGetSymbolAddress((void**)&csrsrc, g_csrsrc);

    cudaFuncSetAttribute(mlp_mma_kernel, cudaFuncAttributeMaxDynamicSharedMemorySize,
                         SMEM_TOTAL_MLP);

    // weight prep + CSR build (once per launch)
    wprep_kernel<<<(6 * D * D + 255) / 256, 256>>>(W1, W2, w1h, w2h);
    cudaMemsetAsync(cnt, 0, (size_t)nNodes * sizeof(int));
    int eb = (nEdges + 255) / 256;
    hist_kernel<<<eb, 256>>>(dst, cnt, tick, nEdges);
    scan_kernel<<<1, 1024>>>(cnt, rowptr, nNodes);
    fill_kernel<<<eb, 256>>>(src, dst, rowptr, tick, csrsrc, nEdges);

    cudaMemsetAsync(pool, 0, (size_t)nGraphs * D * sizeof(float));

    int gatherBlocks = (nNodes * 32 + 255) / 256;
    int nTiles = (nNodes + TILE_M - 1) / TILE_M;
    int mlpGrid = nTiles < 148 ? nTiles : 148;

    const float* xs[3] = { x, x1, x2 };
    float*       xd[3] = { x1, x2, x1 };

    for (int l = 0; l < 3; l++) {
        gather_kernel<<<gatherBlocks, 256>>>(xs[l], rowptr, csrsrc, h, nNodes);
        mlp_mma_kernel<<<mlpGrid, 512, SMEM_TOTAL_MLP>>>(
            h,
            w1h + l * D * D, b1 + l * D,
            w2h + l * D * D, b2 + l * D,
            bns + l * D, bnb + l * D, bnm + l * D, bnv + l * D,
            xd[l], batch, pool, (l == 2) ? 1 : 0, nNodes);
    }

    head_kernel<<<nGraphs, HID>>>(pool, Wh1, bh1, Wh2, bh2, out, nGraphs);
}

// round 15
// speedup vs baseline: 1.3699x; 1.0686x over previous
#include <cuda_runtime.h>
#include <cuda_fp16.h>
#include <math.h>
#include <cstdint>

#define D 128
#define MAX_NODES 50000
#define MAX_EDGES 640000
#define MAX_GRAPHS 500
#define BN_EPS 1e-5f

// ---------------- scratch ----------------------------------------------------
__device__ __half g_h  [MAX_NODES * D];     // gathered input, fp16
__device__ __half g_x1 [MAX_NODES * D];     // layer outputs, fp16
__device__ __half g_x2 [MAX_NODES * D];
__device__ float  g_pool[MAX_GRAPHS * D];
__device__ __half g_w1h[3 * D * D];         // W1^T [n][k] fp16
__device__ __half g_w2h[3 * D * D];
__device__ int    g_cnt [MAX_NODES];
__device__ int    g_rowptr[MAX_NODES + 1];
__device__ int    g_tick[MAX_EDGES];
__device__ int    g_csrsrc[MAX_EDGES];

// ---------------- helpers ----------------------------------------------------
__device__ __forceinline__ void red_add_v2(float* p, float a, float b) {
    asm volatile("red.global.add.v2.f32 [%0], {%1,%2};"
                 :: "l"(p), "f"(a), "f"(b) : "memory");
}
__device__ __forceinline__ void mma_f16(float* d, const uint32_t* a, uint32_t b0, uint32_t b1) {
    asm volatile(
        "mma.sync.aligned.m16n8k16.row.col.f32.f16.f16.f32 "
        "{%0,%1,%2,%3}, {%4,%5,%6,%7}, {%8,%9}, {%0,%1,%2,%3};"
        : "+f"(d[0]), "+f"(d[1]), "+f"(d[2]), "+f"(d[3])
        : "r"(a[0]), "r"(a[1]), "r"(a[2]), "r"(a[3]), "r"(b0), "r"(b1));
}
__device__ __forceinline__ float4 u2_to_f4(uint2 u) {
    float2 lo = __half22float2(*(__half2*)&u.x);
    float2 hi = __half22float2(*(__half2*)&u.y);
    return make_float4(lo.x, lo.y, hi.x, hi.y);
}

// ---------------- CSR build ---------------------------------------------------
__global__ void hist_kernel(const int* __restrict__ dst, int* __restrict__ cnt,
                            int* __restrict__ tick, int nEdges) {
    int e = blockIdx.x * blockDim.x + threadIdx.x;
    if (e < nEdges) tick[e] = atomicAdd(&cnt[dst[e]], 1);
}

__global__ void scan_kernel(const int* __restrict__ cnt, int* __restrict__ rowptr, int n) {
    __shared__ int part[1024];
    int tid = threadIdx.x;
    int chunk = (n + 1023) / 1024;
    int beg = tid * chunk;
    int end = beg + chunk < n ? beg + chunk : n;
    int s = 0;
    for (int i = beg; i < end; i++) s += cnt[i];
    part[tid] = s;
    __syncthreads();
    for (int off = 1; off < 1024; off <<= 1) {
        int v = (tid >= off) ? part[tid - off] : 0;
        __syncthreads();
        part[tid] += v;
        __syncthreads();
    }
    int base = (tid > 0) ? part[tid - 1] : 0;
    for (int i = beg; i < end; i++) {
        rowptr[i] = base;
        base += cnt[i];
    }
    if (tid == 1023) rowptr[n] = part[1023];
}

__global__ void fill_kernel(const int* __restrict__ src, const int* __restrict__ dst,
                            const int* __restrict__ rowptr, const int* __restrict__ tick,
                            int* __restrict__ csrsrc, int nEdges) {
    int e = blockIdx.x * blockDim.x + threadIdx.x;
    if (e < nEdges) csrsrc[rowptr[dst[e]] + tick[e]] = src[e];
}

// ---------------- weight prep: transpose + fp16 ------------------------------
__global__ void wprep_kernel(const float* __restrict__ W1, const float* __restrict__ W2,
                             __half* __restrict__ w1h, __half* __restrict__ w2h) {
    int idx = blockIdx.x * blockDim.x + threadIdx.x;
    if (idx >= 6 * D * D) return;
    int z   = idx >> 14;
    int rem = idx & 16383;
    int k   = rem >> 7;
    int n   = rem & 127;
    const float* W = (z < 3) ? (W1 + z * D * D) : (W2 + (z - 3) * D * D);
    __half*      o = (z < 3) ? (w1h + z * D * D) : (w2h + (z - 3) * D * D);
    o[n * D + k] = __float2half_rn(W[k * D + n]);
}

// ---------------- gather (fp32 input, layer 0) --------------------------------
__global__ __launch_bounds__(256)
void gather_f32_kernel(const float* __restrict__ x,
                       const int* __restrict__ rowptr,
                       const int* __restrict__ csrsrc,
                       __half* __restrict__ h, int nNodes) {
    int gid  = blockIdx.x * blockDim.x + threadIdx.x;
    int node = gid >> 5;
    int lane = gid & 31;
    if (node >= nNodes) return;
    const float4* x4 = (const float4*)x;
    float4 a0 = x4[(size_t)node * 32 + lane];
    float4 a1 = make_float4(0.f, 0.f, 0.f, 0.f);
    float4 a2 = make_float4(0.f, 0.f, 0.f, 0.f);
    float4 a3 = make_float4(0.f, 0.f, 0.f, 0.f);
    int beg = rowptr[node];
    int end = rowptr[node + 1];
    int e = beg;
    for (; e + 3 < end; e += 4) {
        int s0 = csrsrc[e], s1 = csrsrc[e + 1], s2 = csrsrc[e + 2], s3 = csrsrc[e + 3];
        float4 v0 = x4[(size_t)s0 * 32 + lane];
        float4 v1 = x4[(size_t)s1 * 32 + lane];
        float4 v2 = x4[(size_t)s2 * 32 + lane];
        float4 v3 = x4[(size_t)s3 * 32 + lane];
        a0.x += v0.x; a0.y += v0.y; a0.z += v0.z; a0.w += v0.w;
        a1.x += v1.x; a1.y += v1.y; a1.z += v1.z; a1.w += v1.w;
        a2.x += v2.x; a2.y += v2.y; a2.z += v2.z; a2.w += v2.w;
        a3.x += v3.x; a3.y += v3.y; a3.z += v3.z; a3.w += v3.w;
    }
    for (; e < end; e++) {
        int s0 = csrsrc[e];
        float4 v0 = x4[(size_t)s0 * 32 + lane];
        a0.x += v0.x; a0.y += v0.y; a0.z += v0.z; a0.w += v0.w;
    }
    float fx = (a0.x + a1.x) + (a2.x + a3.x);
    float fy = (a0.y + a1.y) + (a2.y + a3.y);
    float fz = (a0.z + a1.z) + (a2.z + a3.z);
    float fw = (a0.w + a1.w) + (a2.w + a3.w);
    __half2* h2 = (__half2*)h;
    h2[(size_t)node * 64 + lane * 2 + 0] = __floats2half2_rn(fx, fy);
    h2[(size_t)node * 64 + lane * 2 + 1] = __floats2half2_rn(fz, fw);
}

// ---------------- gather (fp16 input, layers 1-2) -----------------------------
__global__ __launch_bounds__(256)
void gather_f16_kernel(const __half* __restrict__ x,
                       const int* __restrict__ rowptr,
                       const int* __restrict__ csrsrc,
                       __half* __restrict__ h, int nNodes) {
    int gid  = blockIdx.x * blockDim.x + threadIdx.x;
    int node = gid >> 5;
    int lane = gid & 31;
    if (node >= nNodes) return;
    const uint2* x2 = (const uint2*)x;    // 4 halves per uint2, 32 per row
    float4 a0 = u2_to_f4(x2[(size_t)node * 32 + lane]);
    float4 a1 = make_float4(0.f, 0.f, 0.f, 0.f);
    float4 a2 = make_float4(0.f, 0.f, 0.f, 0.f);
    float4 a3 = make_float4(0.f, 0.f, 0.f, 0.f);
    int beg = rowptr[node];
    int end = rowptr[node + 1];
    int e = beg;
    for (; e + 3 < end; e += 4) {
        int s0 = csrsrc[e], s1 = csrsrc[e + 1], s2 = csrsrc[e + 2], s3 = csrsrc[e + 3];
        float4 v0 = u2_to_f4(x2[(size_t)s0 * 32 + lane]);
        float4 v1 = u2_to_f4(x2[(size_t)s1 * 32 + lane]);
        float4 v2 = u2_to_f4(x2[(size_t)s2 * 32 + lane]);
        float4 v3 = u2_to_f4(x2[(size_t)s3 * 32 + lane]);
        a0.x += v0.x; a0.y += v0.y; a0.z += v0.z; a0.w += v0.w;
        a1.x += v1.x; a1.y += v1.y; a1.z += v1.z; a1.w += v1.w;
        a2.x += v2.x; a2.y += v2.y; a2.z += v2.z; a2.w += v2.w;
        a3.x += v3.x; a3.y += v3.y; a3.z += v3.z; a3.w += v3.w;
    }
    for (; e < end; e++) {
        int s0 = csrsrc[e];
        float4 v0 = u2_to_f4(x2[(size_t)s0 * 32 + lane]);
        a0.x += v0.x; a0.y += v0.y; a0.z += v0.z; a0.w += v0.w;
    }
    float fx = (a0.x + a1.x) + (a2.x + a3.x);
    float fy = (a0.y + a1.y) + (a2.y + a3.y);
    float fz = (a0.z + a1.z) + (a2.z + a3.z);
    float fw = (a0.w + a1.w) + (a2.w + a3.w);
    __half2* h2 = (__half2*)h;
    h2[(size_t)node * 64 + lane * 2 + 0] = __floats2half2_rn(fx, fy);
    h2[(size_t)node * 64 + lane * 2 + 1] = __floats2half2_rn(fz, fw);
}

// ---------------- persistent fused MLP, fp16 m16n8k16 -------------------------
#define TILE_M 128
#define HSTRIDE 136                               // halves per row (pad 8)
#define TILE_HALVES (128 * HSTRIDE)               // 17408
#define P_FLOATS (5 * 128)
#define SMEM_TOTAL_MLP (3 * TILE_HALVES * 2 + P_FLOATS * 4)   // 107008 B

__global__ __launch_bounds__(512, 1)
void mlp_mma_kernel(const __half* __restrict__ hin,
                    const __half* __restrict__ w1h, const float* __restrict__ b1,
                    const __half* __restrict__ w2h, const float* __restrict__ b2,
                    const float* __restrict__ bns, const float* __restrict__ bnb,
                    const float* __restrict__ bnm, const float* __restrict__ bnv,
                    __half* __restrict__ xout,
                    const int* __restrict__ batch, float* __restrict__ pool,
                    int poolMode, int nNodes) {
    extern __shared__ __half smemh[];
    __half* As  = smemh;                      // [128][136]
    __half* B1s = As + TILE_HALVES;
    __half* B2s = B1s + TILE_HALVES;
    float*  sb1 = (float*)(smemh + 3 * TILE_HALVES);
    float*  sb2 = sb1 + 128;
    float*  skk = sb2 + 128;
    float*  smm = skk + 128;
    float*  scc = smm + 128;

    int tid  = threadIdx.x;
    int wid  = tid >> 5;
    int lane = tid & 31;
    int mg   = wid >> 2;        // 0..3 rows mg*32..+31
    int ng   = wid & 3;         // 0..3 cols ng*32..+31
    int gp   = lane >> 2;       // 0..7
    int tq   = lane & 3;        // 0..3

    if (tid < 128) {
        sb1[tid] = b1[tid];
        sb2[tid] = b2[tid];
        skk[tid] = bns[tid] * rsqrtf(bnv[tid] + BN_EPS);
        smm[tid] = bnm[tid];
        scc[tid] = bnb[tid];
    }

    // ---- load both weight matrices ONCE --------------------------------------
    {
        const uint4* w14 = (const uint4*)w1h;   // 16B = 8 halves
        const uint4* w24 = (const uint4*)w2h;
        #pragma unroll
        for (int it = 0; it < 4; it++) {
            int i = tid + it * 512;             // 128 rows * 16 uint4 = 2048
            int row = i >> 4, c16 = i & 15;
            *(uint4*)(B1s + row * HSTRIDE + c16 * 8) = w14[i];
            *(uint4*)(B2s + row * HSTRIDE + c16 * 8) = w24[i];
        }
    }
    __syncthreads();

    const uint4* h4 = (const uint4*)hin;
    int nTiles = (nNodes + TILE_M - 1) / TILE_M;

    for (int tile = blockIdx.x; tile < nTiles; tile += gridDim.x) {
        int row0 = tile * TILE_M;

        // ---- load A tile (fp16) ----------------------------------------------
        #pragma unroll
        for (int it = 0; it < 4; it++) {
            int i = tid + it * 512;
            int row = i >> 4, c16 = i & 15;
            int gr = row0 + row;
            uint4 hv = make_uint4(0u, 0u, 0u, 0u);
            if (gr < nNodes) hv = h4[(size_t)gr * 16 + c16];
            *(uint4*)(As + row * HSTRIDE + c16 * 8) = hv;
        }
        __syncthreads();

        float acc[2][4][4];
        #pragma unroll
        for (int mi = 0; mi < 2; mi++)
            #pragma unroll
            for (int ni = 0; ni < 4; ni++)
                #pragma unroll
                for (int c = 0; c < 4; c++) acc[mi][ni][c] = 0.f;

        // ---- GEMM 1: T = H @ W1 ---------------------------------------------
        #pragma unroll
        for (int s = 0; s < 8; s++) {
            int k0 = s * 16;
            uint32_t afr[2][4], bfr[4][2];
            #pragma unroll
            for (int mi = 0; mi < 2; mi++) {
                const __half* ap = As + (mg * 32 + mi * 16 + gp) * HSTRIDE + k0 + 2 * tq;
                afr[mi][0] = *(const uint32_t*)(ap);
                afr[mi][1] = *(const uint32_t*)(ap + 8 * HSTRIDE);
                afr[mi][2] = *(const uint32_t*)(ap + 8);
                afr[mi][3] = *(const uint32_t*)(ap + 8 * HSTRIDE + 8);
            }
            #pragma unroll
            for (int ni = 0; ni < 4; ni++) {
                const __half* bp = B1s + (ng * 32 + ni * 8 + gp) * HSTRIDE + k0 + 2 * tq;
                bfr[ni][0] = *(const uint32_t*)(bp);
                bfr[ni][1] = *(const uint32_t*)(bp + 8);
            }
            #pragma unroll
            for (int mi = 0; mi < 2; mi++)
                #pragma unroll
                for (int ni = 0; ni < 4; ni++)
                    mma_f16(acc[mi][ni], afr[mi], bfr[ni][0], bfr[ni][1]);
        }
        __syncthreads();

        // ---- epilogue 1: T = fp16(relu(y + b1)) -> As ------------------------
        #pragma unroll
        for (int mi = 0; mi < 2; mi++) {
            #pragma unroll
            for (int ni = 0; ni < 4; ni++) {
                int col = ng * 32 + ni * 8 + 2 * tq;
                int r0  = mg * 32 + mi * 16 + gp;
                float t0 = acc[mi][ni][0] + sb1[col];
                float t1 = acc[mi][ni][1] + sb1[col + 1];
                float t2 = acc[mi][ni][2] + sb1[col];
                float t3 = acc[mi][ni][3] + sb1[col + 1];
                *(__half2*)(As + r0 * HSTRIDE + col) =
                    __floats2half2_rn(t0 > 0.f ? t0 : 0.f, t1 > 0.f ? t1 : 0.f);
                *(__half2*)(As + (r0 + 8) * HSTRIDE + col) =
                    __floats2half2_rn(t2 > 0.f ? t2 : 0.f, t3 > 0.f ? t3 : 0.f);
                acc[mi][ni][0] = 0.f; acc[mi][ni][1] = 0.f;
                acc[mi][ni][2] = 0.f; acc[mi][ni][3] = 0.f;
            }
        }
        __syncthreads();

        // ---- GEMM 2: Y = T @ W2 ---------------------------------------------
        #pragma unroll
        for (int s = 0; s < 8; s++) {
            int k0 = s * 16;
            uint32_t afr[2][4], bfr[4][2];
            #pragma unroll
            for (int mi = 0; mi < 2; mi++) {
                const __half* ap = As + (mg * 32 + mi * 16 + gp) * HSTRIDE + k0 + 2 * tq;
                afr[mi][0] = *(const uint32_t*)(ap);
                afr[mi][1] = *(const uint32_t*)(ap + 8 * HSTRIDE);
                afr[mi][2] = *(const uint32_t*)(ap + 8);
                afr[mi][3] = *(const uint32_t*)(ap + 8 * HSTRIDE + 8);
            }
            #pragma unroll
            for (int ni = 0; ni < 4; ni++) {
                const __half* bp = B2s + (ng * 32 + ni * 8 + gp) * HSTRIDE + k0 + 2 * tq;
                bfr[ni][0] = *(const uint32_t*)(bp);
                bfr[ni][1] = *(const uint32_t*)(bp + 8);
            }
            #pragma unroll
            for (int mi = 0; mi < 2; mi++)
                #pragma unroll
                for (int ni = 0; ni < 4; ni++)
                    mma_f16(acc[mi][ni], afr[mi], bfr[ni][0], bfr[ni][1]);
        }

        // ---- epilogue 2: bias + BN + relu -> fp16 gmem (or fp32 pool RED) ----
        #pragma unroll
        for (int mi = 0; mi < 2; mi++) {
            #pragma unroll
            for (int ni = 0; ni < 4; ni++) {
                int col = ng * 32 + ni * 8 + 2 * tq;
                int r0  = mg * 32 + mi * 16 + gp;
                int gr0 = row0 + r0;
                int gr1 = gr0 + 8;
                float kk0 = skk[col], kk1 = skk[col + 1];
                float t, vx, vy;
                if (gr0 < nNodes) {
                    t = (acc[mi][ni][0] + sb2[col]     - smm[col])     * kk0 + scc[col];
                    vx = t > 0.f ? t : 0.f;
                    t = (acc[mi][ni][1] + sb2[col + 1] - smm[col + 1]) * kk1 + scc[col + 1];
                    vy = t > 0.f ? t : 0.f;
                    if (poolMode) red_add_v2(pool + (size_t)batch[gr0] * D + col, vx, vy);
                    else *(__half2*)(xout + (size_t)gr0 * D + col) = __floats2half2_rn(vx, vy);
                }
                if (gr1 < nNodes) {
                    t = (acc[mi][ni][2] + sb2[col]     - smm[col])     * kk0 + scc[col];
                    vx = t > 0.f ? t : 0.f;
                    t = (acc[mi][ni][3] + sb2[col + 1] - smm[col + 1]) * kk1 + scc[col + 1];
                    vy = t > 0.f ? t : 0.f;
                    if (poolMode) red_add_v2(pool + (size_t)batch[gr1] * D + col, vx, vy);
                    else *(__half2*)(xout + (size_t)gr1 * D + col) = __floats2half2_rn(vx, vy);
                }
            }
        }
        __syncthreads();
    }
}

// ---------------- head --------------------------------------------------------
#define HID 64
#define NCLS 12
__global__ void head_kernel(const float* __restrict__ pool,
                            const float* __restrict__ Wh1, const float* __restrict__ bh1,
                            const float* __restrict__ Wh2, const float* __restrict__ bh2,
                            float* __restrict__ out, int nGraphs) {
    __shared__ float sg[D];
    __shared__ float sh1[HID];
    int g = blockIdx.x;
    if (g >= nGraphs) return;
    int tid = threadIdx.x;
    sg[tid]       = pool[g * D + tid];
    sg[tid + HID] = pool[g * D + tid + HID];
    __syncthreads();
    float a = bh1[tid];
    #pragma unroll 4
    for (int k = 0; k < D; k++) a += sg[k] * Wh1[k * HID + tid];
    sh1[tid] = a > 0.f ? a : 0.f;
    __syncthreads();
    if (tid < NCLS) {
        float o = bh2[tid];
        #pragma unroll
        for (int k = 0; k < HID; k++) o += sh1[k] * Wh2[k * NCLS + tid];
        out[g * NCLS + tid] = 1.f / (1.f + expf(-o));
    }
}

// ---------------- launcher ---------------------------------------------------
extern "C" void kernel_launch(void* const* d_in, const int* in_sizes, int n_in,
                              void* d_out, int out_size) {
    const float* x     = (const float*)d_in[0];
    const int*   ei    = (const int*)d_in[1];
    const int*   batch = (const int*)d_in[2];
    const float* W1    = (const float*)d_in[3];
    const float* b1    = (const float*)d_in[4];
    const float* W2    = (const float*)d_in[5];
    const float* b2    = (const float*)d_in[6];
    const float* bns   = (const float*)d_in[7];
    const float* bnb   = (const float*)d_in[8];
    const float* bnm   = (const float*)d_in[9];
    const float* bnv   = (const float*)d_in[10];
    const float* Wh1   = (const float*)d_in[11];
    const float* bh1   = (const float*)d_in[12];
    const float* Wh2   = (const float*)d_in[13];
    const float* bh2   = (const float*)d_in[14];
    float* out = (float*)d_out;

    int nNodes  = in_sizes[0] / D;
    int nEdges  = in_sizes[1] / 2;
    int nGraphs = out_size / NCLS;

    const int* src = ei;
    const int* dst = ei + nEdges;

    __half *h, *x1, *x2, *w1h, *w2h;
    float *pool;
    int *cnt, *rowptr, *tick, *csrsrc;
    cudaGetSymbolAddress((void**)&h,      g_h);
    cudaGetSymbolAddress((void**)&x1,     g_x1);
    cudaGetSymbolAddress((void**)&x2,     g_x2);
    cudaGetSymbolAddress((void**)&pool,   g_pool);
    cudaGetSymbolAddress((void**)&w1h,    g_w1h);
    cudaGetSymbolAddress((void**)&w2h,    g_w2h);
    cudaGetSymbolAddress((void**)&cnt,    g_cnt);
    cudaGetSymbolAddress((void**)&rowptr, g_rowptr);
    cudaGetSymbolAddress((void**)&tick,   g_tick);
    cudaGetSymbolAddress((void**)&csrsrc, g_csrsrc);

    cudaFuncSetAttribute(mlp_mma_kernel, cudaFuncAttributeMaxDynamicSharedMemorySize,
                         SMEM_TOTAL_MLP);

    // weight prep + CSR build (once per launch)
    wprep_kernel<<<(6 * D * D + 255) / 256, 256>>>(W1, W2, w1h, w2h);
    cudaMemsetAsync(cnt, 0, (size_t)nNodes * sizeof(int));
    int eb = (nEdges + 255) / 256;
    hist_kernel<<<eb, 256>>>(dst, cnt, tick, nEdges);
    scan_kernel<<<1, 1024>>>(cnt, rowptr, nNodes);
    fill_kernel<<<eb, 256>>>(src, dst, rowptr, tick, csrsrc, nEdges);

    cudaMemsetAsync(pool, 0, (size_t)nGraphs * D * sizeof(float));

    int gatherBlocks = (nNodes * 32 + 255) / 256;
    int nTiles = (nNodes + TILE_M - 1) / TILE_M;
    int mlpGrid = nTiles < 148 ? nTiles : 148;

    const __half* xsin[3] = { nullptr, x1, x2 };
    __half*       xd[3]   = { x1, x2, x1 };

    for (int l = 0; l < 3; l++) {
        if (l == 0)
            gather_f32_kernel<<<gatherBlocks, 256>>>(x, rowptr, csrsrc, h, nNodes);
        else
            gather_f16_kernel<<<gatherBlocks, 256>>>(xsin[l], rowptr, csrsrc, h, nNodes);
        mlp_mma_kernel<<<mlpGrid, 512, SMEM_TOTAL_MLP>>>(
            h,
            w1h + l * D * D, b1 + l * D,
            w2h + l * D * D, b2 + l * D,
            bns + l * D, bnb + l * D, bnm + l * D, bnv + l * D,
            xd[l], batch, pool, (l == 2) ? 1 : 0, nNodes);
    }

    head_kernel<<<nGraphs, HID>>>(pool, Wh1, bh1, Wh2, bh2, out, nGraphs);
}

// round 16
// speedup vs baseline: 1.4355x; 1.0478x over previous
#include <cuda_runtime.h>
#include <cuda_fp16.h>
#include <math.h>
#include <cstdint>

#define D 128
#define MAX_NODES 50000
#define MAX_EDGES 640000
#define MAX_GRAPHS 500
#define BN_EPS 1e-5f

// ---------------- scratch ----------------------------------------------------
__device__ __half g_x0h[MAX_NODES * D];     // fp16 copy of input x
__device__ __half g_h  [MAX_NODES * D];     // gathered input, fp16
__device__ __half g_x1 [MAX_NODES * D];     // layer outputs, fp16
__device__ __half g_x2 [MAX_NODES * D];
__device__ float  g_pool[MAX_GRAPHS * D];
__device__ __half g_w1h[3 * D * D];         // W1^T [n][k] fp16
__device__ __half g_w2h[3 * D * D];
__device__ int    g_cnt [MAX_NODES];
__device__ int    g_rowptr[MAX_NODES + 1];
__device__ int    g_tick[MAX_EDGES];
__device__ int    g_csrsrc[MAX_EDGES];

// ---------------- helpers ----------------------------------------------------
__device__ __forceinline__ void red_add_v2(float* p, float a, float b) {
    asm volatile("red.global.add.v2.f32 [%0], {%1,%2};"
                 :: "l"(p), "f"(a), "f"(b) : "memory");
}
__device__ __forceinline__ void mma_f16(float* d, const uint32_t* a, uint32_t b0, uint32_t b1) {
    asm volatile(
        "mma.sync.aligned.m16n8k16.row.col.f32.f16.f16.f32 "
        "{%0,%1,%2,%3}, {%4,%5,%6,%7}, {%8,%9}, {%0,%1,%2,%3};"
        : "+f"(d[0]), "+f"(d[1]), "+f"(d[2]), "+f"(d[3])
        : "r"(a[0]), "r"(a[1]), "r"(a[2]), "r"(a[3]), "r"(b0), "r"(b1));
}
__device__ __forceinline__ float4 u2_to_f4(uint2 u) {
    float2 lo = __half22float2(*(__half2*)&u.x);
    float2 hi = __half22float2(*(__half2*)&u.y);
    return make_float4(lo.x, lo.y, hi.x, hi.y);
}

// ---------------- input conversion fp32 -> fp16 -------------------------------
__global__ void cvt_kernel(const float* __restrict__ x, __half* __restrict__ o, int n4) {
    int i = blockIdx.x * blockDim.x + threadIdx.x;
    if (i >= n4) return;
    float4 v = ((const float4*)x)[i];
    __half2* o2 = (__half2*)o;
    o2[2 * i + 0] = __floats2half2_rn(v.x, v.y);
    o2[2 * i + 1] = __floats2half2_rn(v.z, v.w);
}

// ---------------- CSR build ---------------------------------------------------
__global__ void hist_kernel(const int* __restrict__ dst, int* __restrict__ cnt,
                            int* __restrict__ tick, int nEdges) {
    int e = blockIdx.x * blockDim.x + threadIdx.x;
    if (e < nEdges) tick[e] = atomicAdd(&cnt[dst[e]], 1);
}

__global__ void scan_kernel(const int* __restrict__ cnt, int* __restrict__ rowptr, int n) {
    __shared__ int part[1024];
    int tid = threadIdx.x;
    int chunk = (n + 1023) / 1024;
    int beg = tid * chunk;
    int end = beg + chunk < n ? beg + chunk : n;
    int s = 0;
    for (int i = beg; i < end; i++) s += cnt[i];
    part[tid] = s;
    __syncthreads();
    for (int off = 1; off < 1024; off <<= 1) {
        int v = (tid >= off) ? part[tid - off] : 0;
        __syncthreads();
        part[tid] += v;
        __syncthreads();
    }
    int base = (tid > 0) ? part[tid - 1] : 0;
    for (int i = beg; i < end; i++) {
        rowptr[i] = base;
        base += cnt[i];
    }
    if (tid == 1023) rowptr[n] = part[1023];
}

__global__ void fill_kernel(const int* __restrict__ src, const int* __restrict__ dst,
                            const int* __restrict__ rowptr, const int* __restrict__ tick,
                            int* __restrict__ csrsrc, int nEdges) {
    int e = blockIdx.x * blockDim.x + threadIdx.x;
    if (e < nEdges) csrsrc[rowptr[dst[e]] + tick[e]] = src[e];
}

// ---------------- weight prep: transpose + fp16 ------------------------------
__global__ void wprep_kernel(const float* __restrict__ W1, const float* __restrict__ W2,
                             __half* __restrict__ w1h, __half* __restrict__ w2h) {
    int idx = blockIdx.x * blockDim.x + threadIdx.x;
    if (idx >= 6 * D * D) return;
    int z   = idx >> 14;
    int rem = idx & 16383;
    int k   = rem >> 7;
    int n   = rem & 127;
    const float* W = (z < 3) ? (W1 + z * D * D) : (W2 + (z - 3) * D * D);
    __half*      o = (z < 3) ? (w1h + z * D * D) : (w2h + (z - 3) * D * D);
    o[n * D + k] = __float2half_rn(W[k * D + n]);
}

// ---------------- gather (fp16 input, all layers) -----------------------------
__global__ __launch_bounds__(256)
void gather_f16_kernel(const __half* __restrict__ x,
                       const int* __restrict__ rowptr,
                       const int* __restrict__ csrsrc,
                       __half* __restrict__ h, int nNodes) {
    int gid  = blockIdx.x * blockDim.x + threadIdx.x;
    int node = gid >> 5;
    int lane = gid & 31;
    if (node >= nNodes) return;
    const uint2* x2 = (const uint2*)x;    // 4 halves per uint2, 32 per row
    float4 a0 = u2_to_f4(x2[(size_t)node * 32 + lane]);
    float4 a1 = make_float4(0.f, 0.f, 0.f, 0.f);
    float4 a2 = make_float4(0.f, 0.f, 0.f, 0.f);
    float4 a3 = make_float4(0.f, 0.f, 0.f, 0.f);
    int beg = rowptr[node];
    int end = rowptr[node + 1];
    int e = beg;
    for (; e + 3 < end; e += 4) {
        int s0 = csrsrc[e], s1 = csrsrc[e + 1], s2 = csrsrc[e + 2], s3 = csrsrc[e + 3];
        float4 v0 = u2_to_f4(x2[(size_t)s0 * 32 + lane]);
        float4 v1 = u2_to_f4(x2[(size_t)s1 * 32 + lane]);
        float4 v2 = u2_to_f4(x2[(size_t)s2 * 32 + lane]);
        float4 v3 = u2_to_f4(x2[(size_t)s3 * 32 + lane]);
        a0.x += v0.x; a0.y += v0.y; a0.z += v0.z; a0.w += v0.w;
        a1.x += v1.x; a1.y += v1.y; a1.z += v1.z; a1.w += v1.w;
        a2.x += v2.x; a2.y += v2.y; a2.z += v2.z; a2.w += v2.w;
        a3.x += v3.x; a3.y += v3.y; a3.z += v3.z; a3.w += v3.w;
    }
    for (; e < end; e++) {
        int s0 = csrsrc[e];
        float4 v0 = u2_to_f4(x2[(size_t)s0 * 32 + lane]);
        a0.x += v0.x; a0.y += v0.y; a0.z += v0.z; a0.w += v0.w;
    }
    float fx = (a0.x + a1.x) + (a2.x + a3.x);
    float fy = (a0.y + a1.y) + (a2.y + a3.y);
    float fz = (a0.z + a1.z) + (a2.z + a3.z);
    float fw = (a0.w + a1.w) + (a2.w + a3.w);
    __half2* h2 = (__half2*)h;
    h2[(size_t)node * 64 + lane * 2 + 0] = __floats2half2_rn(fx, fy);
    h2[(size_t)node * 64 + lane * 2 + 1] = __floats2half2_rn(fz, fw);
}

// ---------------- persistent fused MLP, fp16 m16n8k16, A prefetch -------------
#define TILE_M 128
#define HSTRIDE 136                               // halves per row (pad 8)
#define TILE_HALVES (128 * HSTRIDE)               // 17408
#define P_FLOATS (5 * 128)
#define SMEM_TOTAL_MLP (3 * TILE_HALVES * 2 + P_FLOATS * 4)   // 107008 B

__global__ __launch_bounds__(512, 1)
void mlp_mma_kernel(const __half* __restrict__ hin,
                    const __half* __restrict__ w1h, const float* __restrict__ b1,
                    const __half* __restrict__ w2h, const float* __restrict__ b2,
                    const float* __restrict__ bns, const float* __restrict__ bnb,
                    const float* __restrict__ bnm, const float* __restrict__ bnv,
                    __half* __restrict__ xout,
                    const int* __restrict__ batch, float* __restrict__ pool,
                    int poolMode, int nNodes) {
    extern __shared__ __half smemh[];
    __half* As  = smemh;                      // [128][136]
    __half* B1s = As + TILE_HALVES;
    __half* B2s = B1s + TILE_HALVES;
    float*  sb1 = (float*)(smemh + 3 * TILE_HALVES);
    float*  sb2 = sb1 + 128;
    float*  skk = sb2 + 128;
    float*  smm = skk + 128;
    float*  scc = smm + 128;

    int tid  = threadIdx.x;
    int wid  = tid >> 5;
    int lane = tid & 31;
    int mg   = wid >> 2;        // 0..3 rows mg*32..+31
    int ng   = wid & 3;         // 0..3 cols ng*32..+31
    int gp   = lane >> 2;       // 0..7
    int tq   = lane & 3;        // 0..3

    if (tid < 128) {
        sb1[tid] = b1[tid];
        sb2[tid] = b2[tid];
        skk[tid] = bns[tid] * rsqrtf(bnv[tid] + BN_EPS);
        smm[tid] = bnm[tid];
        scc[tid] = bnb[tid];
    }

    // ---- load both weight matrices ONCE --------------------------------------
    {
        const uint4* w14 = (const uint4*)w1h;   // 16B = 8 halves
        const uint4* w24 = (const uint4*)w2h;
        #pragma unroll
        for (int it = 0; it < 4; it++) {
            int i = tid + it * 512;             // 128 rows * 16 uint4 = 2048
            int row = i >> 4, c16 = i & 15;
            *(uint4*)(B1s + row * HSTRIDE + c16 * 8) = w14[i];
            *(uint4*)(B2s + row * HSTRIDE + c16 * 8) = w24[i];
        }
    }

    const uint4* h4 = (const uint4*)hin;
    int nTiles = (nNodes + TILE_M - 1) / TILE_M;
    int stride = gridDim.x;

    // ---- preload first tile into registers -----------------------------------
    uint4 pf[4];
    {
        int tile0 = blockIdx.x;
        #pragma unroll
        for (int it = 0; it < 4; it++) {
            int i = tid + it * 512;
            int row = i >> 4, c16 = i & 15;
            int gr = tile0 * TILE_M + row;
            pf[it] = make_uint4(0u, 0u, 0u, 0u);
            if (tile0 < nTiles && gr < nNodes) pf[it] = h4[(size_t)gr * 16 + c16];
        }
    }
    __syncthreads();   // weights + params visible

    for (int tile = blockIdx.x; tile < nTiles; tile += stride) {
        int row0 = tile * TILE_M;

        // ---- store prefetched A tile to smem ---------------------------------
        #pragma unroll
        for (int it = 0; it < 4; it++) {
            int i = tid + it * 512;
            int row = i >> 4, c16 = i & 15;
            *(uint4*)(As + row * HSTRIDE + c16 * 8) = pf[it];
        }
        __syncthreads();

        // ---- issue prefetch for next tile (overlaps both GEMMs) --------------
        {
            int nt = tile + stride;
            if (nt < nTiles) {
                #pragma unroll
                for (int it = 0; it < 4; it++) {
                    int i = tid + it * 512;
                    int row = i >> 4, c16 = i & 15;
                    int gr = nt * TILE_M + row;
                    pf[it] = make_uint4(0u, 0u, 0u, 0u);
                    if (gr < nNodes) pf[it] = h4[(size_t)gr * 16 + c16];
                }
            }
        }

        float acc[2][4][4];
        #pragma unroll
        for (int mi = 0; mi < 2; mi++)
            #pragma unroll
            for (int ni = 0; ni < 4; ni++)
                #pragma unroll
                for (int c = 0; c < 4; c++) acc[mi][ni][c] = 0.f;

        // ---- GEMM 1: T = H @ W1 ---------------------------------------------
        #pragma unroll
        for (int s = 0; s < 8; s++) {
            int k0 = s * 16;
            uint32_t afr[2][4], bfr[4][2];
            #pragma unroll
            for (int mi = 0; mi < 2; mi++) {
                const __half* ap = As + (mg * 32 + mi * 16 + gp) * HSTRIDE + k0 + 2 * tq;
                afr[mi][0] = *(const uint32_t*)(ap);
                afr[mi][1] = *(const uint32_t*)(ap + 8 * HSTRIDE);
                afr[mi][2] = *(const uint32_t*)(ap + 8);
                afr[mi][3] = *(const uint32_t*)(ap + 8 * HSTRIDE + 8);
            }
            #pragma unroll
            for (int ni = 0; ni < 4; ni++) {
                const __half* bp = B1s + (ng * 32 + ni * 8 + gp) * HSTRIDE + k0 + 2 * tq;
                bfr[ni][0] = *(const uint32_t*)(bp);
                bfr[ni][1] = *(const uint32_t*)(bp + 8);
            }
            #pragma unroll
            for (int mi = 0; mi < 2; mi++)
                #pragma unroll
                for (int ni = 0; ni < 4; ni++)
                    mma_f16(acc[mi][ni], afr[mi], bfr[ni][0], bfr[ni][1]);
        }
        __syncthreads();

        // ---- epilogue 1: T = fp16(relu(y + b1)) -> As ------------------------
        #pragma unroll
        for (int mi = 0; mi < 2; mi++) {
            #pragma unroll
            for (int ni = 0; ni < 4; ni++) {
                int col = ng * 32 + ni * 8 + 2 * tq;
                int r0  = mg * 32 + mi * 16 + gp;
                float t0 = acc[mi][ni][0] + sb1[col];
                float t1 = acc[mi][ni][1] + sb1[col + 1];
                float t2 = acc[mi][ni][2] + sb1[col];
                float t3 = acc[mi][ni][3] + sb1[col + 1];
                *(__half2*)(As + r0 * HSTRIDE + col) =
                    __floats2half2_rn(t0 > 0.f ? t0 : 0.f, t1 > 0.f ? t1 : 0.f);
                *(__half2*)(As + (r0 + 8) * HSTRIDE + col) =
                    __floats2half2_rn(t2 > 0.f ? t2 : 0.f, t3 > 0.f ? t3 : 0.f);
                acc[mi][ni][0] = 0.f; acc[mi][ni][1] = 0.f;
                acc[mi][ni][2] = 0.f; acc[mi][ni][3] = 0.f;
            }
        }
        __syncthreads();

        // ---- GEMM 2: Y = T @ W2 ---------------------------------------------
        #pragma unroll
        for (int s = 0; s < 8; s++) {
            int k0 = s * 16;
            uint32_t afr[2][4], bfr[4][2];
            #pragma unroll
            for (int mi = 0; mi < 2; mi++) {
                const __half* ap = As + (mg * 32 + mi * 16 + gp) * HSTRIDE + k0 + 2 * tq;
                afr[mi][0] = *(const uint32_t*)(ap);
                afr[mi][1] = *(const uint32_t*)(ap + 8 * HSTRIDE);
                afr[mi][2] = *(const uint32_t*)(ap + 8);
                afr[mi][3] = *(const uint32_t*)(ap + 8 * HSTRIDE + 8);
            }
            #pragma unroll
            for (int ni = 0; ni < 4; ni++) {
                const __half* bp = B2s + (ng * 32 + ni * 8 + gp) * HSTRIDE + k0 + 2 * tq;
                bfr[ni][0] = *(const uint32_t*)(bp);
                bfr[ni][1] = *(const uint32_t*)(bp + 8);
            }
            #pragma unroll
            for (int mi = 0; mi < 2; mi++)
                #pragma unroll
                for (int ni = 0; ni < 4; ni++)
                    mma_f16(acc[mi][ni], afr[mi], bfr[ni][0], bfr[ni][1]);
        }

        // ---- epilogue 2: bias + BN + relu -> fp16 gmem (or fp32 pool RED) ----
        #pragma unroll
        for (int mi = 0; mi < 2; mi++) {
            #pragma unroll
            for (int ni = 0; ni < 4; ni++) {
                int col = ng * 32 + ni * 8 + 2 * tq;
                int r0  = mg * 32 + mi * 16 + gp;
                int gr0 = row0 + r0;
                int gr1 = gr0 + 8;
                float kk0 = skk[col], kk1 = skk[col + 1];
                float t, vx, vy;
                if (gr0 < nNodes) {
                    t = (acc[mi][ni][0] + sb2[col]     - smm[col])     * kk0 + scc[col];
                    vx = t > 0.f ? t : 0.f;
                    t = (acc[mi][ni][1] + sb2[col + 1] - smm[col + 1]) * kk1 + scc[col + 1];
                    vy = t > 0.f ? t : 0.f;
                    if (poolMode) red_add_v2(pool + (size_t)batch[gr0] * D + col, vx, vy);
                    else *(__half2*)(xout + (size_t)gr0 * D + col) = __floats2half2_rn(vx, vy);
                }
                if (gr1 < nNodes) {
                    t = (acc[mi][ni][2] + sb2[col]     - smm[col])     * kk0 + scc[col];
                    vx = t > 0.f ? t : 0.f;
                    t = (acc[mi][ni][3] + sb2[col + 1] - smm[col + 1]) * kk1 + scc[col + 1];
                    vy = t > 0.f ? t : 0.f;
                    if (poolMode) red_add_v2(pool + (size_t)batch[gr1] * D + col, vx, vy);
                    else *(__half2*)(xout + (size_t)gr1 * D + col) = __floats2half2_rn(vx, vy);
                }
            }
        }
        __syncthreads();   // GEMM2's As reads done before next tile's store
    }
}

// ---------------- head --------------------------------------------------------
#define HID 64
#define NCLS 12
__global__ void head_kernel(const float* __restrict__ pool,
                            const float* __restrict__ Wh1, const float* __restrict__ bh1,
                            const float* __restrict__ Wh2, const float* __restrict__ bh2,
                            float* __restrict__ out, int nGraphs) {
    __shared__ float sg[D];
    __shared__ float sh1[HID];
    int g = blockIdx.x;
    if (g >= nGraphs) return;
    int tid = threadIdx.x;
    sg[tid]       = pool[g * D + tid];
    sg[tid + HID] = pool[g * D + tid + HID];
    __syncthreads();
    float a = bh1[tid];
    #pragma unroll 4
    for (int k = 0; k < D; k++) a += sg[k] * Wh1[k * HID + tid];
    sh1[tid] = a > 0.f ? a : 0.f;
    __syncthreads();
    if (tid < NCLS) {
        float o = bh2[tid];
        #pragma unroll
        for (int k = 0; k < HID; k++) o += sh1[k] * Wh2[k * NCLS + tid];
        out[g * NCLS + tid] = 1.f / (1.f + expf(-o));
    }
}

// ---------------- launcher ---------------------------------------------------
extern "C" void kernel_launch(void* const* d_in, const int* in_sizes, int n_in,
                              void* d_out, int out_size) {
    const float* x     = (const float*)d_in[0];
    const int*   ei    = (const int*)d_in[1];
    const int*   batch = (const int*)d_in[2];
    const float* W1    = (const float*)d_in[3];
    const float* b1    = (const float*)d_in[4];
    const float* W2    = (const float*)d_in[5];
    const float* b2    = (const float*)d_in[6];
    const float* bns   = (const float*)d_in[7];
    const float* bnb   = (const float*)d_in[8];
    const float* bnm   = (const float*)d_in[9];
    const float* bnv   = (const float*)d_in[10];
    const float* Wh1   = (const float*)d_in[11];
    const float* bh1   = (const float*)d_in[12];
    const float* Wh2   = (const float*)d_in[13];
    const float* bh2   = (const float*)d_in[14];
    float* out = (float*)d_out;

    int nNodes  = in_sizes[0] / D;
    int nEdges  = in_sizes[1] / 2;
    int nGraphs = out_size / NCLS;

    const int* src = ei;
    const int* dst = ei + nEdges;

    __half *x0h, *h, *x1, *x2, *w1h, *w2h;
    float *pool;
    int *cnt, *rowptr, *tick, *csrsrc;
    cudaGetSymbolAddress((void**)&x0h,    g_x0h);
    cudaGetSymbolAddress((void**)&h,      g_h);
    cudaGetSymbolAddress((void**)&x1,     g_x1);
    cudaGetSymbolAddress((void**)&x2,     g_x2);
    cudaGetSymbolAddress((void**)&pool,   g_pool);
    cudaGetSymbolAddress((void**)&w1h,    g_w1h);
    cudaGetSymbolAddress((void**)&w2h,    g_w2h);
    cudaGetSymbolAddress((void**)&cnt,    g_cnt);
    cudaGetSymbolAddress((void**)&rowptr, g_rowptr);
    cudaGetSymbolAddress((void**)&tick,   g_tick);
    cudaGetSymbolAddress((void**)&csrsrc, g_csrsrc);

    cudaFuncSetAttribute(mlp_mma_kernel, cudaFuncAttributeMaxDynamicSharedMemorySize,
                         SMEM_TOTAL_MLP);

    // prep: input fp16 copy + weights + CSR build (once per launch)
    int n4 = nNodes * D / 4;
    cvt_kernel<<<(n4 + 255) / 256, 256>>>(x, x0h, n4);
    wprep_kernel<<<(6 * D * D + 255) / 256, 256>>>(W1, W2, w1h, w2h);
    cudaMemsetAsync(cnt, 0, (size_t)nNodes * sizeof(int));
    int eb = (nEdges + 255) / 256;
    hist_kernel<<<eb, 256>>>(dst, cnt, tick, nEdges);
    scan_kernel<<<1, 1024>>>(cnt, rowptr, nNodes);
    fill_kernel<<<eb, 256>>>(src, dst, rowptr, tick, csrsrc, nEdges);

    cudaMemsetAsync(pool, 0, (size_t)nGraphs * D * sizeof(float));

    int gatherBlocks = (nNodes * 32 + 255) / 256;
    int nTiles = (nNodes + TILE_M - 1) / TILE_M;
    int mlpGrid = nTiles < 148 ? nTiles : 148;

    const __half* xsin[3] = { x0h, x1, x2 };
    __half*       xd[3]   = { x1, x2, x1 };

    for (int l = 0; l < 3; l++) {
        gather_f16_kernel<<<gatherBlocks, 256>>>(xsin[l], rowptr, csrsrc, h, nNodes);
        mlp_mma_kernel<<<mlpGrid, 512, SMEM_TOTAL_MLP>>>(
            h,
            w1h + l * D * D, b1 + l * D,
            w2h + l * D * D, b2 + l * D,
            bns + l * D, bnb + l * D, bnm + l * D, bnv + l * D,
            xd[l], batch, pool, (l == 2) ? 1 : 0, nNodes);
    }

    head_kernel<<<nGraphs, HID>>>(pool, Wh1, bh1, Wh2, bh2, out, nGraphs);
}

// round 17
// speedup vs baseline: 1.6822x; 1.1719x over previous
#include <cuda_runtime.h>
#include <cuda_fp16.h>
#include <math.h>
#include <cstdint>

#define D 128
#define MAX_NODES 50000
#define MAX_EDGES 640000
#define MAX_GRAPHS 500
#define BN_EPS 1e-5f

// ---------------- scratch ----------------------------------------------------
__device__ __half g_x0h[MAX_NODES * D];     // fp16 copy of input x
__device__ __half g_h  [MAX_NODES * D];     // gathered input, fp16
__device__ __half g_x1 [MAX_NODES * D];     // layer outputs, fp16
__device__ __half g_x2 [MAX_NODES * D];
__device__ float  g_pool[MAX_GRAPHS * D];
__device__ __half g_w1h[3 * D * D];         // W1^T [n][k] fp16
__device__ __half g_w2h[3 * D * D];
__device__ int    g_cnt [MAX_NODES];
__device__ int    g_rowptr[MAX_NODES + 1];
__device__ int    g_excl[MAX_NODES];
__device__ int    g_bsum[64];
__device__ int    g_boff[64];
__device__ int    g_tick[MAX_EDGES];
__device__ int    g_csrsrc[MAX_EDGES];

// ---------------- helpers ----------------------------------------------------
__device__ __forceinline__ void red_add_v2(float* p, float a, float b) {
    asm volatile("red.global.add.v2.f32 [%0], {%1,%2};"
                 :: "l"(p), "f"(a), "f"(b) : "memory");
}
__device__ __forceinline__ void mma_f16(float* d, const uint32_t* a, uint32_t b0, uint32_t b1) {
    asm volatile(
        "mma.sync.aligned.m16n8k16.row.col.f32.f16.f16.f32 "
        "{%0,%1,%2,%3}, {%4,%5,%6,%7}, {%8,%9}, {%0,%1,%2,%3};"
        : "+f"(d[0]), "+f"(d[1]), "+f"(d[2]), "+f"(d[3])
        : "r"(a[0]), "r"(a[1]), "r"(a[2]), "r"(a[3]), "r"(b0), "r"(b1));
}
__device__ __forceinline__ float4 u2_to_f4(uint2 u) {
    float2 lo = __half22float2(*(__half2*)&u.x);
    float2 hi = __half22float2(*(__half2*)&u.y);
    return make_float4(lo.x, lo.y, hi.x, hi.y);
}

// ---------------- input conversion fp32 -> fp16 -------------------------------
__global__ void cvt_kernel(const float* __restrict__ x, __half* __restrict__ o, int n4) {
    int i = blockIdx.x * blockDim.x + threadIdx.x;
    if (i >= n4) return;
    float4 v = ((const float4*)x)[i];
    __half2* o2 = (__half2*)o;
    o2[2 * i + 0] = __floats2half2_rn(v.x, v.y);
    o2[2 * i + 1] = __floats2half2_rn(v.z, v.w);
}

// ---------------- CSR build ---------------------------------------------------
__global__ void hist_kernel(const int* __restrict__ dst, int* __restrict__ cnt,
                            int* __restrict__ tick, int nEdges) {
    int e = blockIdx.x * blockDim.x + threadIdx.x;
    if (e < nEdges) tick[e] = atomicAdd(&cnt[dst[e]], 1);
}

// parallel scan, pass A: per-block exclusive prefix + block total
__global__ void scanA_kernel(const int* __restrict__ cnt, int* __restrict__ excl,
                             int* __restrict__ bsum, int n) {
    __shared__ int sh[1024];
    int tid = threadIdx.x;
    int i = blockIdx.x * 1024 + tid;
    int v = (i < n) ? cnt[i] : 0;
    sh[tid] = v;
    __syncthreads();
    for (int off = 1; off < 1024; off <<= 1) {
        int t = (tid >= off) ? sh[tid - off] : 0;
        __syncthreads();
        sh[tid] += t;
        __syncthreads();
    }
    if (i < n) excl[i] = sh[tid] - v;
    if (tid == 1023) bsum[blockIdx.x] = sh[1023];
}

// pass B: scan block totals (nb <= 64), write offsets + rowptr[n]
__global__ void scanB_kernel(const int* __restrict__ bsum, int* __restrict__ boff,
                             int* __restrict__ rowptr, int nb, int n) {
    __shared__ int sh[64];
    int tid = threadIdx.x;
    int v = (tid < nb) ? bsum[tid] : 0;
    sh[tid] = v;
    __syncthreads();
    for (int off = 1; off < 64; off <<= 1) {
        int t = (tid >= off) ? sh[tid - off] : 0;
        __syncthreads();
        sh[tid] += t;
        __syncthreads();
    }
    if (tid < nb) boff[tid] = sh[tid] - v;
    if (tid == nb - 1) rowptr[n] = sh[tid];
}

// pass C: combine
__global__ void scanC_kernel(const int* __restrict__ excl, const int* __restrict__ boff,
                             int* __restrict__ rowptr, int n) {
    int i = blockIdx.x * blockDim.x + threadIdx.x;
    if (i < n) rowptr[i] = excl[i] + boff[i >> 10];
}

__global__ void fill_kernel(const int* __restrict__ src, const int* __restrict__ dst,
                            const int* __restrict__ rowptr, const int* __restrict__ tick,
                            int* __restrict__ csrsrc, int nEdges) {
    int e = blockIdx.x * blockDim.x + threadIdx.x;
    if (e < nEdges) csrsrc[rowptr[dst[e]] + tick[e]] = src[e];
}

// ---------------- weight prep: transpose + fp16 ------------------------------
__global__ void wprep_kernel(const float* __restrict__ W1, const float* __restrict__ W2,
                             __half* __restrict__ w1h, __half* __restrict__ w2h) {
    int idx = blockIdx.x * blockDim.x + threadIdx.x;
    if (idx >= 6 * D * D) return;
    int z   = idx >> 14;
    int rem = idx & 16383;
    int k   = rem >> 7;
    int n   = rem & 127;
    const float* W = (z < 3) ? (W1 + z * D * D) : (W2 + (z - 3) * D * D);
    __half*      o = (z < 3) ? (w1h + z * D * D) : (w2h + (z - 3) * D * D);
    o[n * D + k] = __float2half_rn(W[k * D + n]);
}

// ---------------- gather (fp16 input, all layers) -----------------------------
__global__ __launch_bounds__(256)
void gather_f16_kernel(const __half* __restrict__ x,
                       const int* __restrict__ rowptr,
                       const int* __restrict__ csrsrc,
                       __half* __restrict__ h, int nNodes) {
    int gid  = blockIdx.x * blockDim.x + threadIdx.x;
    int node = gid >> 5;
    int lane = gid & 31;
    if (node >= nNodes) return;
    const uint2* x2 = (const uint2*)x;    // 4 halves per uint2, 32 per row
    float4 a0 = u2_to_f4(x2[(size_t)node * 32 + lane]);
    float4 a1 = make_float4(0.f, 0.f, 0.f, 0.f);
    float4 a2 = make_float4(0.f, 0.f, 0.f, 0.f);
    float4 a3 = make_float4(0.f, 0.f, 0.f, 0.f);
    int beg = rowptr[node];
    int end = rowptr[node + 1];
    int e = beg;
    for (; e + 3 < end; e += 4) {
        int s0 = csrsrc[e], s1 = csrsrc[e + 1], s2 = csrsrc[e + 2], s3 = csrsrc[e + 3];
        float4 v0 = u2_to_f4(x2[(size_t)s0 * 32 + lane]);
        float4 v1 = u2_to_f4(x2[(size_t)s1 * 32 + lane]);
        float4 v2 = u2_to_f4(x2[(size_t)s2 * 32 + lane]);
        float4 v3 = u2_to_f4(x2[(size_t)s3 * 32 + lane]);
        a0.x += v0.x; a0.y += v0.y; a0.z += v0.z; a0.w += v0.w;
        a1.x += v1.x; a1.y += v1.y; a1.z += v1.z; a1.w += v1.w;
        a2.x += v2.x; a2.y += v2.y; a2.z += v2.z; a2.w += v2.w;
        a3.x += v3.x; a3.y += v3.y; a3.z += v3.z; a3.w += v3.w;
    }
    for (; e < end; e++) {
        int s0 = csrsrc[e];
        float4 v0 = u2_to_f4(x2[(size_t)s0 * 32 + lane]);
        a0.x += v0.x; a0.y += v0.y; a0.z += v0.z; a0.w += v0.w;
    }
    float fx = (a0.x + a1.x) + (a2.x + a3.x);
    float fy = (a0.y + a1.y) + (a2.y + a3.y);
    float fz = (a0.z + a1.z) + (a2.z + a3.z);
    float fw = (a0.w + a1.w) + (a2.w + a3.w);
    __half2* h2 = (__half2*)h;
    h2[(size_t)node * 64 + lane * 2 + 0] = __floats2half2_rn(fx, fy);
    h2[(size_t)node * 64 + lane * 2 + 1] = __floats2half2_rn(fz, fw);
}

// ---------------- persistent fused MLP, fp16 m16n8k16, A prefetch -------------
#define TILE_M 128
#define HSTRIDE 136                               // halves per row (pad 8)
#define TILE_HALVES (128 * HSTRIDE)               // 17408
#define P_FLOATS (5 * 128)
#define SMEM_TOTAL_MLP (3 * TILE_HALVES * 2 + P_FLOATS * 4)   // 107008 B

__global__ __launch_bounds__(512, 1)
void mlp_mma_kernel(const __half* __restrict__ hin,
                    const __half* __restrict__ w1h, const float* __restrict__ b1,
                    const __half* __restrict__ w2h, const float* __restrict__ b2,
                    const float* __restrict__ bns, const float* __restrict__ bnb,
                    const float* __restrict__ bnm, const float* __restrict__ bnv,
                    __half* __restrict__ xout,
                    const int* __restrict__ batch, float* __restrict__ pool,
                    int poolMode, int nNodes) {
    extern __shared__ __half smemh[];
    __half* As  = smemh;                      // [128][136]
    __half* B1s = As + TILE_HALVES;
    __half* B2s = B1s + TILE_HALVES;
    float*  sb1 = (float*)(smemh + 3 * TILE_HALVES);
    float*  sb2 = sb1 + 128;
    float*  skk = sb2 + 128;
    float*  smm = skk + 128;
    float*  scc = smm + 128;

    int tid  = threadIdx.x;
    int wid  = tid >> 5;
    int lane = tid & 31;
    int mg   = wid >> 2;        // 0..3 rows mg*32..+31
    int ng   = wid & 3;         // 0..3 cols ng*32..+31
    int gp   = lane >> 2;       // 0..7
    int tq   = lane & 3;        // 0..3

    if (tid < 128) {
        sb1[tid] = b1[tid];
        sb2[tid] = b2[tid];
        skk[tid] = bns[tid] * rsqrtf(bnv[tid] + BN_EPS);
        smm[tid] = bnm[tid];
        scc[tid] = bnb[tid];
    }

    // ---- load both weight matrices ONCE --------------------------------------
    {
        const uint4* w14 = (const uint4*)w1h;   // 16B = 8 halves
        const uint4* w24 = (const uint4*)w2h;
        #pragma unroll
        for (int it = 0; it < 4; it++) {
            int i = tid + it * 512;             // 128 rows * 16 uint4 = 2048
            int row = i >> 4, c16 = i & 15;
            *(uint4*)(B1s + row * HSTRIDE + c16 * 8) = w14[i];
            *(uint4*)(B2s + row * HSTRIDE + c16 * 8) = w24[i];
        }
    }

    const uint4* h4 = (const uint4*)hin;
    int nTiles = (nNodes + TILE_M - 1) / TILE_M;
    int stride = gridDim.x;

    // ---- preload first tile into registers -----------------------------------
    uint4 pf[4];
    {
        int tile0 = blockIdx.x;
        #pragma unroll
        for (int it = 0; it < 4; it++) {
            int i = tid + it * 512;
            int row = i >> 4, c16 = i & 15;
            int gr = tile0 * TILE_M + row;
            pf[it] = make_uint4(0u, 0u, 0u, 0u);
            if (tile0 < nTiles && gr < nNodes) pf[it] = h4[(size_t)gr * 16 + c16];
        }
    }
    __syncthreads();   // weights + params visible

    for (int tile = blockIdx.x; tile < nTiles; tile += stride) {
        int row0 = tile * TILE_M;

        // ---- store prefetched A tile to smem ---------------------------------
        #pragma unroll
        for (int it = 0; it < 4; it++) {
            int i = tid + it * 512;
            int row = i >> 4, c16 = i & 15;
            *(uint4*)(As + row * HSTRIDE + c16 * 8) = pf[it];
        }
        __syncthreads();

        // ---- issue prefetch for next tile (overlaps both GEMMs) --------------
        {
            int nt = tile + stride;
            if (nt < nTiles) {
                #pragma unroll
                for (int it = 0; it < 4; it++) {
                    int i = tid + it * 512;
                    int row = i >> 4, c16 = i & 15;
                    int gr = nt * TILE_M + row;
                    pf[it] = make_uint4(0u, 0u, 0u, 0u);
                    if (gr < nNodes) pf[it] = h4[(size_t)gr * 16 + c16];
                }
            }
        }

        float acc[2][4][4];
        #pragma unroll
        for (int mi = 0; mi < 2; mi++)
            #pragma unroll
            for (int ni = 0; ni < 4; ni++)
                #pragma unroll
                for (int c = 0; c < 4; c++) acc[mi][ni][c] = 0.f;

        // ---- GEMM 1: T = H @ W1 ---------------------------------------------
        #pragma unroll
        for (int s = 0; s < 8; s++) {
            int k0 = s * 16;
            uint32_t afr[2][4], bfr[4][2];
            #pragma unroll
            for (int mi = 0; mi < 2; mi++) {
                const __half* ap = As + (mg * 32 + mi * 16 + gp) * HSTRIDE + k0 + 2 * tq;
                afr[mi][0] = *(const uint32_t*)(ap);
                afr[mi][1] = *(const uint32_t*)(ap + 8 * HSTRIDE);
                afr[mi][2] = *(const uint32_t*)(ap + 8);
                afr[mi][3] = *(const uint32_t*)(ap + 8 * HSTRIDE + 8);
            }
            #pragma unroll
            for (int ni = 0; ni < 4; ni++) {
                const __half* bp = B1s + (ng * 32 + ni * 8 + gp) * HSTRIDE + k0 + 2 * tq;
                bfr[ni][0] = *(const uint32_t*)(bp);
                bfr[ni][1] = *(const uint32_t*)(bp + 8);
            }
            #pragma unroll
            for (int mi = 0; mi < 2; mi++)
                #pragma unroll
                for (int ni = 0; ni < 4; ni++)
                    mma_f16(acc[mi][ni], afr[mi], bfr[ni][0], bfr[ni][1]);
        }
        __syncthreads();

        // ---- epilogue 1: T = fp16(relu(y + b1)) -> As ------------------------
        #pragma unroll
        for (int mi = 0; mi < 2; mi++) {
            #pragma unroll
            for (int ni = 0; ni < 4; ni++) {
                int col = ng * 32 + ni * 8 + 2 * tq;
                int r0  = mg * 32 + mi * 16 + gp;
                float t0 = acc[mi][ni][0] + sb1[col];
                float t1 = acc[mi][ni][1] + sb1[col + 1];
                float t2 = acc[mi][ni][2] + sb1[col];
                float t3 = acc[mi][ni][3] + sb1[col + 1];
                *(__half2*)(As + r0 * HSTRIDE + col) =
                    __floats2half2_rn(t0 > 0.f ? t0 : 0.f, t1 > 0.f ? t1 : 0.f);
                *(__half2*)(As + (r0 + 8) * HSTRIDE + col) =
                    __floats2half2_rn(t2 > 0.f ? t2 : 0.f, t3 > 0.f ? t3 : 0.f);
                acc[mi][ni][0] = 0.f; acc[mi][ni][1] = 0.f;
                acc[mi][ni][2] = 0.f; acc[mi][ni][3] = 0.f;
            }
        }
        __syncthreads();

        // ---- GEMM 2: Y = T @ W2 ---------------------------------------------
        #pragma unroll
        for (int s = 0; s < 8; s++) {
            int k0 = s * 16;
            uint32_t afr[2][4], bfr[4][2];
            #pragma unroll
            for (int mi = 0; mi < 2; mi++) {
                const __half* ap = As + (mg * 32 + mi * 16 + gp) * HSTRIDE + k0 + 2 * tq;
                afr[mi][0] = *(const uint32_t*)(ap);
                afr[mi][1] = *(const uint32_t*)(ap + 8 * HSTRIDE);
                afr[mi][2] = *(const uint32_t*)(ap + 8);
                afr[mi][3] = *(const uint32_t*)(ap + 8 * HSTRIDE + 8);
            }
            #pragma unroll
            for (int ni = 0; ni < 4; ni++) {
                const __half* bp = B2s + (ng * 32 + ni * 8 + gp) * HSTRIDE + k0 + 2 * tq;
                bfr[ni][0] = *(const uint32_t*)(bp);
                bfr[ni][1] = *(const uint32_t*)(bp + 8);
            }
            #pragma unroll
            for (int mi = 0; mi < 2; mi++)
                #pragma unroll
                for (int ni = 0; ni < 4; ni++)
                    mma_f16(acc[mi][ni], afr[mi], bfr[ni][0], bfr[ni][1]);
        }

        // ---- epilogue 2: bias + BN + relu -> fp16 gmem (or fp32 pool RED) ----
        #pragma unroll
        for (int mi = 0; mi < 2; mi++) {
            #pragma unroll
            for (int ni = 0; ni < 4; ni++) {
                int col = ng * 32 + ni * 8 + 2 * tq;
                int r0  = mg * 32 + mi * 16 + gp;
                int gr0 = row0 + r0;
                int gr1 = gr0 + 8;
                float kk0 = skk[col], kk1 = skk[col + 1];
                float t, vx, vy;
                if (gr0 < nNodes) {
                    t = (acc[mi][ni][0] + sb2[col]     - smm[col])     * kk0 + scc[col];
                    vx = t > 0.f ? t : 0.f;
                    t = (acc[mi][ni][1] + sb2[col + 1] - smm[col + 1]) * kk1 + scc[col + 1];
                    vy = t > 0.f ? t : 0.f;
                    if (poolMode) red_add_v2(pool + (size_t)batch[gr0] * D + col, vx, vy);
                    else *(__half2*)(xout + (size_t)gr0 * D + col) = __floats2half2_rn(vx, vy);
                }
                if (gr1 < nNodes) {
                    t = (acc[mi][ni][2] + sb2[col]     - smm[col])     * kk0 + scc[col];
                    vx = t > 0.f ? t : 0.f;
                    t = (acc[mi][ni][3] + sb2[col + 1] - smm[col + 1]) * kk1 + scc[col + 1];
                    vy = t > 0.f ? t : 0.f;
                    if (poolMode) red_add_v2(pool + (size_t)batch[gr1] * D + col, vx, vy);
                    else *(__half2*)(xout + (size_t)gr1 * D + col) = __floats2half2_rn(vx, vy);
                }
            }
        }
        __syncthreads();   // GEMM2's As reads done before next tile's store
    }
}

// ---------------- head --------------------------------------------------------
#define HID 64
#define NCLS 12
__global__ void head_kernel(const float* __restrict__ pool,
                            const float* __restrict__ Wh1, const float* __restrict__ bh1,
                            const float* __restrict__ Wh2, const float* __restrict__ bh2,
                            float* __restrict__ out, int nGraphs) {
    __shared__ float sg[D];
    __shared__ float sh1[HID];
    int g = blockIdx.x;
    if (g >= nGraphs) return;
    int tid = threadIdx.x;
    sg[tid]       = pool[g * D + tid];
    sg[tid + HID] = pool[g * D + tid + HID];
    __syncthreads();
    float a = bh1[tid];
    #pragma unroll 4
    for (int k = 0; k < D; k++) a += sg[k] * Wh1[k * HID + tid];
    sh1[tid] = a > 0.f ? a : 0.f;
    __syncthreads();
    if (tid < NCLS) {
        float o = bh2[tid];
        #pragma unroll
        for (int k = 0; k < HID; k++) o += sh1[k] * Wh2[k * NCLS + tid];
        out[g * NCLS + tid] = 1.f / (1.f + expf(-o));
    }
}

// ---------------- launcher ---------------------------------------------------
extern "C" void kernel_launch(void* const* d_in, const int* in_sizes, int n_in,
                              void* d_out, int out_size) {
    const float* x     = (const float*)d_in[0];
    const int*   ei    = (const int*)d_in[1];
    const int*   batch = (const int*)d_in[2];
    const float* W1    = (const float*)d_in[3];
    const float* b1    = (const float*)d_in[4];
    const float* W2    = (const float*)d_in[5];
    const float* b2    = (const float*)d_in[6];
    const float* bns   = (const float*)d_in[7];
    const float* bnb   = (const float*)d_in[8];
    const float* bnm   = (const float*)d_in[9];
    const float* bnv   = (const float*)d_in[10];
    const float* Wh1   = (const float*)d_in[11];
    const float* bh1   = (const float*)d_in[12];
    const float* Wh2   = (const float*)d_in[13];
    const float* bh2   = (const float*)d_in[14];
    float* out = (float*)d_out;

    int nNodes  = in_sizes[0] / D;
    int nEdges  = in_sizes[1] / 2;
    int nGraphs = out_size / NCLS;

    const int* src = ei;
    const int* dst = ei + nEdges;

    __half *x0h, *h, *x1, *x2, *w1h, *w2h;
    float *pool;
    int *cnt, *rowptr, *excl, *bsum, *boff, *tick, *csrsrc;
    cudaGetSymbolAddress((void**)&x0h,    g_x0h);
    cudaGetSymbolAddress((void**)&h,      g_h);
    cudaGetSymbolAddress((void**)&x1,     g_x1);
    cudaGetSymbolAddress((void**)&x2,     g_x2);
    cudaGetSymbolAddress((void**)&pool,   g_pool);
    cudaGetSymbolAddress((void**)&w1h,    g_w1h);
    cudaGetSymbolAddress((void**)&w2h,    g_w2h);
    cudaGetSymbolAddress((void**)&cnt,    g_cnt);
    cudaGetSymbolAddress((void**)&rowptr, g_rowptr);
    cudaGetSymbolAddress((void**)&excl,   g_excl);
    cudaGetSymbolAddress((void**)&bsum,   g_bsum);
    cudaGetSymbolAddress((void**)&boff,   g_boff);
    cudaGetSymbolAddress((void**)&tick,   g_tick);
    cudaGetSymbolAddress((void**)&csrsrc, g_csrsrc);

    cudaFuncSetAttribute(mlp_mma_kernel, cudaFuncAttributeMaxDynamicSharedMemorySize,
                         SMEM_TOTAL_MLP);

    // prep: input fp16 copy + weights + CSR build (once per launch)
    int n4 = nNodes * D / 4;
    cvt_kernel<<<(n4 + 255) / 256, 256>>>(x, x0h, n4);
    wprep_kernel<<<(6 * D * D + 255) / 256, 256>>>(W1, W2, w1h, w2h);
    cudaMemsetAsync(cnt, 0, (size_t)nNodes * sizeof(int));
    int eb = (nEdges + 255) / 256;
    hist_kernel<<<eb, 256>>>(dst, cnt, tick, nEdges);
    int nb = (nNodes + 1023) / 1024;
    scanA_kernel<<<nb, 1024>>>(cnt, excl, bsum, nNodes);
    scanB_kernel<<<1, 64>>>(bsum, boff, rowptr, nb, nNodes);
    scanC_kernel<<<(nNodes + 255) / 256, 256>>>(excl, boff, rowptr, nNodes);
    fill_kernel<<<eb, 256>>>(src, dst, rowptr, tick, csrsrc, nEdges);

    cudaMemsetAsync(pool, 0, (size_t)nGraphs * D * sizeof(float));

    int gatherBlocks = (nNodes * 32 + 255) / 256;
    int nTiles = (nNodes + TILE_M - 1) / TILE_M;
    int mlpGrid = nTiles < 148 ? nTiles : 148;

    const __half* xsin[3] = { x0h, x1, x2 };
    __half*       xd[3]   = { x1, x2, x1 };

    for (int l = 0; l < 3; l++) {
        gather_f16_kernel<<<gatherBlocks, 256>>>(xsin[l], rowptr, csrsrc, h, nNodes);
        mlp_mma_kernel<<<mlpGrid, 512, SMEM_TOTAL_MLP>>>(
            h,
            w1h + l * D * D, b1 + l * D,
            w2h + l * D * D, b2 + l * D,
            bns + l * D, bnb + l * D, bnm + l * D, bnv + l * D,
            xd[l], batch, pool, (l == 2) ? 1 : 0, nNodes);
    }

    head_kernel<<<nGraphs, HID>>>(pool, Wh1, bh1, Wh2, bh2, out, nGraphs);
}